// round 7
// baseline (speedup 1.0000x reference)
#include <cuda_runtime.h>
#include <cuda_bf16.h>
#include <stdint.h>

#define NPTS   65536
#define CCH    512
#define NH     8
#define PW     128
#define DHD    64
#define RPEN   31
#define PBND   15
#define SCALE  0.125f

// ---------------------------------------------------------------------------
// Static device scratch
// ---------------------------------------------------------------------------
__device__ __nv_bfloat16 g_qhi[(size_t)NPTS * 1536];   // serialized qkv hi/lo
__device__ __nv_bfloat16 g_qlo[(size_t)NPTS * 1536];
__device__ __nv_bfloat16 g_fhi[(size_t)NPTS * 512];    // feat[order] hi/lo
__device__ __nv_bfloat16 g_flo[(size_t)NPTS * 512];
__device__ __nv_bfloat16 g_ahi[(size_t)NPTS * 512];    // attn-out (point order)
__device__ __nv_bfloat16 g_alo[(size_t)NPTS * 512];
__device__ __nv_bfloat16 g_wqh[1536 * 512];
__device__ __nv_bfloat16 g_wql[1536 * 512];
__device__ __nv_bfloat16 g_wph[512 * 512];
__device__ __nv_bfloat16 g_wpl[512 * 512];

// ---------------------------------------------------------------------------
// PTX helpers (sm_100-legal)
// ---------------------------------------------------------------------------
__device__ __forceinline__ uint32_t smem_u32(const void* p) {
    uint32_t a;
    asm("{ .reg .u64 t; cvta.to.shared.u64 t, %1; cvt.u32.u64 %0, t; }"
        : "=r"(a) : "l"(p));
    return a;
}
__device__ __forceinline__ void cp16(uint32_t dst, const void* src) {
    asm volatile("cp.async.cg.shared.global [%0], [%1], 16;"
                 :: "r"(dst), "l"(src) : "memory");
}
__device__ __forceinline__ void cp_commit() {
    asm volatile("cp.async.commit_group;" ::: "memory");
}
template <int N>
__device__ __forceinline__ void cp_wait() {
    asm volatile("cp.async.wait_group %0;" :: "n"(N) : "memory");
}
__device__ __forceinline__ void ldm_x4(uint32_t* r, uint32_t addr) {
    asm volatile("ldmatrix.sync.aligned.m8n8.x4.shared.b16 {%0,%1,%2,%3}, [%4];"
                 : "=r"(r[0]), "=r"(r[1]), "=r"(r[2]), "=r"(r[3]) : "r"(addr));
}
__device__ __forceinline__ void ldm_x4_t(uint32_t* r, uint32_t addr) {
    asm volatile("ldmatrix.sync.aligned.m8n8.x4.trans.shared.b16 {%0,%1,%2,%3}, [%4];"
                 : "=r"(r[0]), "=r"(r[1]), "=r"(r[2]), "=r"(r[3]) : "r"(addr));
}
__device__ __forceinline__ void mma16816(float* d, const uint32_t* a, const uint32_t* b) {
    asm volatile(
        "mma.sync.aligned.m16n8k16.row.col.f32.bf16.bf16.f32 "
        "{%0,%1,%2,%3}, {%4,%5,%6,%7}, {%8,%9}, {%0,%1,%2,%3};"
        : "+f"(d[0]), "+f"(d[1]), "+f"(d[2]), "+f"(d[3])
        : "r"(a[0]), "r"(a[1]), "r"(a[2]), "r"(a[3]), "r"(b[0]), "r"(b[1]));
}

// ---------------------------------------------------------------------------
// bf16-split kernels
// ---------------------------------------------------------------------------
__global__ void split_gather_k(const float* __restrict__ src, const int* __restrict__ gidx,
                               __nv_bfloat16* __restrict__ hi, __nv_bfloat16* __restrict__ lo)
{
    int i = blockIdx.x * 256 + threadIdx.x;
    int m = i >> 7;
    int c = (i & 127) << 2;
    float4 v = *(const float4*)(src + (size_t)gidx[m] * 512 + c);
    float xs[4] = {v.x, v.y, v.z, v.w};
    __align__(8) __nv_bfloat16 hb[4], lb[4];
#pragma unroll
    for (int j = 0; j < 4; j++) {
        hb[j] = __float2bfloat16(xs[j]);
        lb[j] = __float2bfloat16(xs[j] - __bfloat162float(hb[j]));
    }
    size_t o = (size_t)m * 512 + c;
    *(uint2*)(hi + o) = *(uint2*)hb;
    *(uint2*)(lo + o) = *(uint2*)lb;
}

__global__ void split_plain_k(const float* __restrict__ src,
                              __nv_bfloat16* __restrict__ hi, __nv_bfloat16* __restrict__ lo,
                              int n4)
{
    int i = blockIdx.x * 256 + threadIdx.x;
    if (i >= n4) return;
    float4 v = *(const float4*)(src + (size_t)i * 4);
    float xs[4] = {v.x, v.y, v.z, v.w};
    __align__(8) __nv_bfloat16 hb[4], lb[4];
#pragma unroll
    for (int j = 0; j < 4; j++) {
        hb[j] = __float2bfloat16(xs[j]);
        lb[j] = __float2bfloat16(xs[j] - __bfloat162float(hb[j]));
    }
    size_t o = (size_t)i * 4;
    *(uint2*)(hi + o) = *(uint2*)hb;
    *(uint2*)(lo + o) = *(uint2*)lb;
}

// ---------------------------------------------------------------------------
// mma.sync bf16 3-term GEMM. Output either f32 (C) or bf16 hi/lo (Chi/Clo).
// Single-barrier-per-chunk cp.async pipeline.
// ---------------------------------------------------------------------------
#define GK       512
#define BK       32
#define NCH      (GK / BK)
#define TROW_B   80
#define TILE_B   (128 * TROW_B)
#define STAGE_B  (4 * TILE_B)
#define GSMEM    (2 * STAGE_B)

__global__ __launch_bounds__(256, 2)
void gemm_bf16x3(const __nv_bfloat16* __restrict__ Ah, const __nv_bfloat16* __restrict__ Al,
                 const __nv_bfloat16* __restrict__ Bh, const __nv_bfloat16* __restrict__ Bl,
                 const float* __restrict__ bias, float* __restrict__ C,
                 __nv_bfloat16* __restrict__ Chi, __nv_bfloat16* __restrict__ Clo, int Ntot)
{
    extern __shared__ __align__(128) char sm[];
    const uint32_t smb = smem_u32(sm);

    const int tid  = threadIdx.x;
    const int lane = tid & 31;
    const int warp = tid >> 5;
    const int wm   = warp >> 2;
    const int wn   = warp & 3;
    const int m0   = blockIdx.y * 128;
    const int n0   = blockIdx.x * 128;

    const __nv_bfloat16* gsrc[4] = {
        Ah + (size_t)m0 * GK, Al + (size_t)m0 * GK,
        Bh + (size_t)n0 * GK, Bl + (size_t)n0 * GK
    };

    auto load_stage = [&](int c) {
        const uint32_t sb = smb + (c & 1) * STAGE_B;
#pragma unroll
        for (int t = 0; t < 4; t++) {
            const __nv_bfloat16* g = gsrc[t] + c * BK;
#pragma unroll
            for (int i = 0; i < 2; i++) {
                int idx = i * 256 + tid;
                int r = idx >> 2, s = idx & 3;
                cp16(sb + t * TILE_B + r * TROW_B + s * 16,
                     g + (size_t)r * GK + s * 8);
            }
        }
    };

    float acc[4][4][4];
#pragma unroll
    for (int i = 0; i < 4; i++)
#pragma unroll
        for (int j = 0; j < 4; j++)
#pragma unroll
            for (int e = 0; e < 4; e++) acc[i][j][e] = 0.f;

    const int arow  = lane & 15;
    const int acolb = (lane >> 4) * 16;
    const int brow  = (lane & 7) + (lane >> 4) * 8;
    const int bkb   = ((lane >> 3) & 1) * 16;

    load_stage(0);
    cp_commit();

    for (int c = 0; c < NCH; c++) {
        // Own-group wait THEN barrier: all warps' copies for chunk c are
        // landed and published. Prefetch c+1 (other buffer) after the
        // barrier: its previous readers (chunk c-1 MMAs) are provably done.
        cp_wait<0>();
        __syncthreads();
        if (c + 1 < NCH) { load_stage(c + 1); cp_commit(); }

        const uint32_t sb  = smb + (c & 1) * STAGE_B;
        const uint32_t sAh = sb;
        const uint32_t sAl = sb + TILE_B;
        const uint32_t sBh = sb + 2 * TILE_B;
        const uint32_t sBl = sb + 3 * TILE_B;

#pragma unroll
        for (int ks = 0; ks < 2; ks++) {
            const int kb = ks * 32;
            uint32_t ah[4][4], al[4][4], bh[2][4], bl[2][4];
#pragma unroll
            for (int mi = 0; mi < 4; mi++)
                ldm_x4(ah[mi], sAh + (wm * 64 + mi * 16 + arow) * TROW_B + kb + acolb);
#pragma unroll
            for (int jj = 0; jj < 2; jj++)
                ldm_x4(bh[jj], sBh + (wn * 32 + jj * 16 + brow) * TROW_B + kb + bkb);
#pragma unroll
            for (int mi = 0; mi < 4; mi++)
#pragma unroll
                for (int nj = 0; nj < 4; nj++)
                    mma16816(acc[mi][nj], ah[mi], &bh[nj >> 1][(nj & 1) * 2]);
#pragma unroll
            for (int jj = 0; jj < 2; jj++)
                ldm_x4(bl[jj], sBl + (wn * 32 + jj * 16 + brow) * TROW_B + kb + bkb);
#pragma unroll
            for (int mi = 0; mi < 4; mi++)
#pragma unroll
                for (int nj = 0; nj < 4; nj++)
                    mma16816(acc[mi][nj], ah[mi], &bl[nj >> 1][(nj & 1) * 2]);
#pragma unroll
            for (int mi = 0; mi < 4; mi++)
                ldm_x4(al[mi], sAl + (wm * 64 + mi * 16 + arow) * TROW_B + kb + acolb);
#pragma unroll
            for (int mi = 0; mi < 4; mi++)
#pragma unroll
                for (int nj = 0; nj < 4; nj++)
                    mma16816(acc[mi][nj], al[mi], &bh[nj >> 1][(nj & 1) * 2]);
        }
    }

    const int gr = lane >> 2;
    const int gc = (lane & 3) * 2;
    float2 bv[4];
#pragma unroll
    for (int nj = 0; nj < 4; nj++)
        bv[nj] = *(const float2*)(bias + n0 + wn * 32 + nj * 8 + gc);

    if (Chi) {
#pragma unroll
        for (int mi = 0; mi < 4; mi++) {
            int rowa = m0 + wm * 64 + mi * 16 + gr;
#pragma unroll
            for (int nj = 0; nj < 4; nj++) {
                int col = n0 + wn * 32 + nj * 8 + gc;
                float v0 = acc[mi][nj][0] + bv[nj].x;
                float v1 = acc[mi][nj][1] + bv[nj].y;
                float v2 = acc[mi][nj][2] + bv[nj].x;
                float v3 = acc[mi][nj][3] + bv[nj].y;
                __nv_bfloat162 h01, h23, l01, l23;
                h01.x = __float2bfloat16(v0); h01.y = __float2bfloat16(v1);
                l01.x = __float2bfloat16(v0 - __bfloat162float(h01.x));
                l01.y = __float2bfloat16(v1 - __bfloat162float(h01.y));
                h23.x = __float2bfloat16(v2); h23.y = __float2bfloat16(v3);
                l23.x = __float2bfloat16(v2 - __bfloat162float(h23.x));
                l23.y = __float2bfloat16(v3 - __bfloat162float(h23.y));
                *(__nv_bfloat162*)(Chi + (size_t)rowa * Ntot + col)       = h01;
                *(__nv_bfloat162*)(Clo + (size_t)rowa * Ntot + col)       = l01;
                *(__nv_bfloat162*)(Chi + (size_t)(rowa + 8) * Ntot + col) = h23;
                *(__nv_bfloat162*)(Clo + (size_t)(rowa + 8) * Ntot + col) = l23;
            }
        }
    } else {
#pragma unroll
        for (int mi = 0; mi < 4; mi++) {
            int rowa = m0 + wm * 64 + mi * 16 + gr;
#pragma unroll
            for (int nj = 0; nj < 4; nj++) {
                int col = n0 + wn * 32 + nj * 8 + gc;
                float2 lo = make_float2(acc[mi][nj][0] + bv[nj].x, acc[mi][nj][1] + bv[nj].y);
                float2 hi = make_float2(acc[mi][nj][2] + bv[nj].x, acc[mi][nj][3] + bv[nj].y);
                *(float2*)(C + (size_t)rowa * Ntot + col)       = lo;
                *(float2*)(C + (size_t)(rowa + 8) * Ntot + col) = hi;
            }
        }
    }
}

// ---------------------------------------------------------------------------
// mma.sync attention per (window, head).
// ---------------------------------------------------------------------------
#define ARS      144                    // smem row stride bytes (72 bf16)
#define AT_B     (128 * ARS)
#define OFF_QH   0
#define OFF_QL   (1 * AT_B)
#define OFF_KH   (2 * AT_B)
#define OFF_KL   (3 * AT_B)
#define OFF_VH   (4 * AT_B)
#define OFF_VL   (5 * AT_B)
#define OFF_RPE  (6 * AT_B)
#define OFF_GC   (OFF_RPE + 96 * 4)
#define OFF_ORD  (OFF_GC + 3 * 128 * 4)
#define ASMEM    (OFF_ORD + 128 * 4)

__global__ __launch_bounds__(256, 1)
void attn_mma(const __nv_bfloat16* __restrict__ qhi, const __nv_bfloat16* __restrict__ qlo,
              const int* __restrict__ order, const int* __restrict__ gcoord,
              const float* __restrict__ rpe,
              __nv_bfloat16* __restrict__ ohi, __nv_bfloat16* __restrict__ olo)
{
    extern __shared__ __align__(128) char sm[];
    const uint32_t smb = smem_u32(sm);
    float* rpeS = (float*)(sm + OFF_RPE);
    int*   gcs  = (int*)(sm + OFF_GC);
    int*   ords = (int*)(sm + OFF_ORD);

    const int w    = blockIdx.x;
    const int hh   = blockIdx.y;
    const int tid  = threadIdx.x;
    const int lane = tid & 31;
    const int wid  = tid >> 5;
    const int wb   = w * PW;

    // ---- stage q/k/v hi+lo via cp.async ----
    const __nv_bfloat16* baseh = qhi + (size_t)wb * 1536 + hh * 64;
    const __nv_bfloat16* basel = qlo + (size_t)wb * 1536 + hh * 64;
    const __nv_bfloat16* srcp[6] = {
        baseh, basel, baseh + 512, basel + 512, baseh + 1024, basel + 1024
    };
#pragma unroll
    for (int m = 0; m < 6; m++) {
        uint32_t dstb = smb + m * AT_B;
#pragma unroll
        for (int i = 0; i < 4; i++) {
            int idx = i * 256 + tid;
            int r = idx >> 3, s = idx & 7;
            cp16(dstb + r * ARS + s * 16, srcp[m] + (size_t)r * 1536 + s * 8);
        }
    }
    cp_commit();

    for (int i = tid; i < 128; i += 256) {
        int g = order[wb + i];
        ords[i] = g;
        gcs[0 * 128 + i] = gcoord[g * 3 + 0];
        gcs[1 * 128 + i] = gcoord[g * 3 + 1];
        gcs[2 * 128 + i] = gcoord[g * 3 + 2];
    }
    for (int i = tid; i < 3 * RPEN; i += 256) rpeS[i] = rpe[i * NH + hh];
    cp_wait<0>();
    __syncthreads();

    const int w16   = wid * 16;
    const int arow  = lane & 15;
    const int acolb = (lane >> 4) * 16;
    const int brow  = (lane & 7) + (lane >> 4) * 8;
    const int bkb   = ((lane >> 3) & 1) * 16;

    // ---- S = scale*QK^T : 3-term ----
    uint32_t qh4[4][4], ql4[4][4];
#pragma unroll
    for (int ks = 0; ks < 4; ks++) {
        ldm_x4(qh4[ks], smb + OFF_QH + (w16 + arow) * ARS + ks * 32 + acolb);
        ldm_x4(ql4[ks], smb + OFF_QL + (w16 + arow) * ARS + ks * 32 + acolb);
    }
    float s[16][4];
#pragma unroll
    for (int nj = 0; nj < 16; nj++)
#pragma unroll
        for (int e = 0; e < 4; e++) s[nj][e] = 0.f;

#pragma unroll
    for (int ks = 0; ks < 4; ks++) {
#pragma unroll
        for (int ng = 0; ng < 8; ng++) {
            uint32_t kh[4], kl[4];
            ldm_x4(kh, smb + OFF_KH + (ng * 16 + brow) * ARS + ks * 32 + bkb);
            ldm_x4(kl, smb + OFF_KL + (ng * 16 + brow) * ARS + ks * 32 + bkb);
            mma16816(s[2 * ng],     qh4[ks], kh + 0);
            mma16816(s[2 * ng + 1], qh4[ks], kh + 2);
            mma16816(s[2 * ng],     qh4[ks], kl + 0);
            mma16816(s[2 * ng + 1], qh4[ks], kl + 2);
            mma16816(s[2 * ng],     ql4[ks], kh + 0);
            mma16816(s[2 * ng + 1], ql4[ks], kh + 2);
        }
    }

    // ---- scale + RPE bias (fragment layout) ----
    const int gr  = lane >> 2;
    const int gc2 = (lane & 3) * 2;
    const int r1  = w16 + gr, r2 = r1 + 8;
    const int qa0 = gcs[0 * 128 + r1], qa1 = gcs[1 * 128 + r1], qa2 = gcs[2 * 128 + r1];
    const int qb0 = gcs[0 * 128 + r2], qb1 = gcs[1 * 128 + r2], qb2 = gcs[2 * 128 + r2];

#pragma unroll
    for (int nj = 0; nj < 16; nj++) {
        int c0 = nj * 8 + gc2;
#pragma unroll
        for (int cc = 0; cc < 2; cc++) {
            int c  = c0 + cc;
            int k0 = gcs[0 * 128 + c], k1 = gcs[1 * 128 + c], k2 = gcs[2 * 128 + c];
            int ia0 = min(max(qa0 - k0, -PBND), PBND) + PBND;
            int ia1 = min(max(qa1 - k1, -PBND), PBND) + PBND + RPEN;
            int ia2 = min(max(qa2 - k2, -PBND), PBND) + PBND + 2 * RPEN;
            int ib0 = min(max(qb0 - k0, -PBND), PBND) + PBND;
            int ib1 = min(max(qb1 - k1, -PBND), PBND) + PBND + RPEN;
            int ib2 = min(max(qb2 - k2, -PBND), PBND) + PBND + 2 * RPEN;
            s[nj][cc]     = s[nj][cc]     * SCALE + rpeS[ia0] + rpeS[ia1] + rpeS[ia2];
            s[nj][2 + cc] = s[nj][2 + cc] * SCALE + rpeS[ib0] + rpeS[ib1] + rpeS[ib2];
        }
    }

    // ---- softmax over keys (rows r1, r2) ----
    float m1 = -1e30f, m2 = -1e30f;
#pragma unroll
    for (int nj = 0; nj < 16; nj++) {
        m1 = fmaxf(m1, fmaxf(s[nj][0], s[nj][1]));
        m2 = fmaxf(m2, fmaxf(s[nj][2], s[nj][3]));
    }
    m1 = fmaxf(m1, __shfl_xor_sync(0xffffffffu, m1, 1));
    m1 = fmaxf(m1, __shfl_xor_sync(0xffffffffu, m1, 2));
    m2 = fmaxf(m2, __shfl_xor_sync(0xffffffffu, m2, 1));
    m2 = fmaxf(m2, __shfl_xor_sync(0xffffffffu, m2, 2));
    float s1 = 0.f, s2 = 0.f;
#pragma unroll
    for (int nj = 0; nj < 16; nj++) {
        s[nj][0] = __expf(s[nj][0] - m1); s1 += s[nj][0];
        s[nj][1] = __expf(s[nj][1] - m1); s1 += s[nj][1];
        s[nj][2] = __expf(s[nj][2] - m2); s2 += s[nj][2];
        s[nj][3] = __expf(s[nj][3] - m2); s2 += s[nj][3];
    }
    s1 += __shfl_xor_sync(0xffffffffu, s1, 1);
    s1 += __shfl_xor_sync(0xffffffffu, s1, 2);
    s2 += __shfl_xor_sync(0xffffffffu, s2, 1);
    s2 += __shfl_xor_sync(0xffffffffu, s2, 2);
    float i1 = 1.0f / s1, i2 = 1.0f / s2;

    // ---- P -> bf16 hi/lo A-fragments (C-frag == A-frag layout) ----
    uint32_t pha[8][4], pla[8][4];
#pragma unroll
    for (int kt = 0; kt < 8; kt++) {
#pragma unroll
        for (int half = 0; half < 2; half++) {
            int f = 2 * kt + half;
            float v0 = s[f][0] * i1, v1 = s[f][1] * i1;
            float v2 = s[f][2] * i2, v3 = s[f][3] * i2;
            __nv_bfloat162 h01, h23, l01, l23;
            h01.x = __float2bfloat16(v0); h01.y = __float2bfloat16(v1);
            l01.x = __float2bfloat16(v0 - __bfloat162float(h01.x));
            l01.y = __float2bfloat16(v1 - __bfloat162float(h01.y));
            h23.x = __float2bfloat16(v2); h23.y = __float2bfloat16(v3);
            l23.x = __float2bfloat16(v2 - __bfloat162float(h23.x));
            l23.y = __float2bfloat16(v3 - __bfloat162float(h23.y));
            pha[kt][0 + 2 * half] = *(uint32_t*)&h01;
            pha[kt][1 + 2 * half] = *(uint32_t*)&h23;
            pla[kt][0 + 2 * half] = *(uint32_t*)&l01;
            pla[kt][1 + 2 * half] = *(uint32_t*)&l23;
        }
    }

    // ---- O = P V : 3-term, V B-frags via ldmatrix.trans ----
    float o[8][4];
#pragma unroll
    for (int nj = 0; nj < 8; nj++)
#pragma unroll
        for (int e = 0; e < 4; e++) o[nj][e] = 0.f;

    const int vrow = ((lane >> 3) & 1) * 8 + (lane & 7);
    const int vcb  = (lane >> 4) * 16;
#pragma unroll
    for (int kt = 0; kt < 8; kt++) {
#pragma unroll
        for (int ng = 0; ng < 4; ng++) {
            uint32_t vh[4], vl[4];
            ldm_x4_t(vh, smb + OFF_VH + (kt * 16 + vrow) * ARS + ng * 32 + vcb);
            ldm_x4_t(vl, smb + OFF_VL + (kt * 16 + vrow) * ARS + ng * 32 + vcb);
            mma16816(o[2 * ng],     pha[kt], vh + 0);
            mma16816(o[2 * ng + 1], pha[kt], vh + 2);
            mma16816(o[2 * ng],     pha[kt], vl + 0);
            mma16816(o[2 * ng + 1], pha[kt], vl + 2);
            mma16816(o[2 * ng],     pla[kt], vh + 0);
            mma16816(o[2 * ng + 1], pla[kt], vh + 2);
        }
    }

    // ---- epilogue: bf16 split, scatter through order ----
    const int d1 = ords[r1], d2 = ords[r2];
#pragma unroll
    for (int nj = 0; nj < 8; nj++) {
        int col = nj * 8 + gc2;
        size_t o1 = (size_t)d1 * 512 + hh * 64 + col;
        size_t o2 = (size_t)d2 * 512 + hh * 64 + col;
        __nv_bfloat162 h01, h23, l01, l23;
        h01.x = __float2bfloat16(o[nj][0]); h01.y = __float2bfloat16(o[nj][1]);
        l01.x = __float2bfloat16(o[nj][0] - __bfloat162float(h01.x));
        l01.y = __float2bfloat16(o[nj][1] - __bfloat162float(h01.y));
        h23.x = __float2bfloat16(o[nj][2]); h23.y = __float2bfloat16(o[nj][3]);
        l23.x = __float2bfloat16(o[nj][2] - __bfloat162float(h23.x));
        l23.y = __float2bfloat16(o[nj][3] - __bfloat162float(h23.y));
        *(__nv_bfloat162*)(ohi + o1) = h01;
        *(__nv_bfloat162*)(olo + o1) = l01;
        *(__nv_bfloat162*)(ohi + o2) = h23;
        *(__nv_bfloat162*)(olo + o2) = l23;
    }
}

// ---------------------------------------------------------------------------
extern "C" void kernel_launch(void* const* d_in, const int* in_sizes, int n_in,
                              void* d_out, int out_size)
{
    const float* feat    = (const float*)d_in[0];
    const float* w_qkv   = (const float*)d_in[1];
    const float* b_qkv   = (const float*)d_in[2];
    const float* w_proj  = (const float*)d_in[3];
    const float* b_proj  = (const float*)d_in[4];
    const float* rpe     = (const float*)d_in[5];
    const int*   gcoord  = (const int*)d_in[6];
    const int*   order   = (const int*)d_in[7];
    float*       out     = (float*)d_out;

    __nv_bfloat16 *qhi, *qlo, *fhi, *flo, *ahi, *alo, *wqh, *wql, *wph, *wpl;
    cudaGetSymbolAddress((void**)&qhi, g_qhi);
    cudaGetSymbolAddress((void**)&qlo, g_qlo);
    cudaGetSymbolAddress((void**)&fhi, g_fhi);
    cudaGetSymbolAddress((void**)&flo, g_flo);
    cudaGetSymbolAddress((void**)&ahi, g_ahi);
    cudaGetSymbolAddress((void**)&alo, g_alo);
    cudaGetSymbolAddress((void**)&wqh, g_wqh);
    cudaGetSymbolAddress((void**)&wql, g_wql);
    cudaGetSymbolAddress((void**)&wph, g_wph);
    cudaGetSymbolAddress((void**)&wpl, g_wpl);

    cudaFuncSetAttribute(gemm_bf16x3, cudaFuncAttributeMaxDynamicSharedMemorySize, GSMEM);
    cudaFuncSetAttribute(attn_mma, cudaFuncAttributeMaxDynamicSharedMemorySize, ASMEM);

    // 1) bf16 splits
    split_gather_k<<<NPTS * 128 / 256, 256>>>(feat, order, fhi, flo);
    split_plain_k<<<(1536 * 512 / 4) / 256, 256>>>(w_qkv, wqh, wql, 1536 * 512 / 4);
    split_plain_k<<<(512 * 512 / 4) / 256, 256>>>(w_proj, wph, wpl, 512 * 512 / 4);

    // 2) QKV projection -> serialized qkv bf16 hi/lo (bias added)
    gemm_bf16x3<<<dim3(1536 / 128, NPTS / 128), 256, GSMEM>>>(
        fhi, flo, wqh, wql, b_qkv, nullptr, qhi, qlo, 1536);

    // 3) mma attention; writes bf16-split output scattered to point order
    attn_mma<<<dim3(NPTS / PW, NH), 256, ASMEM>>>(
        qhi, qlo, order, gcoord, rpe, ahi, alo);

    // 4) Output projection -> f32 d_out
    gemm_bf16x3<<<dim3(512 / 128, NPTS / 128), 256, GSMEM>>>(
        ahi, alo, wph, wpl, b_proj, out, nullptr, nullptr, 512);
}

// round 8
// speedup vs baseline: 1.3542x; 1.3542x over previous
#include <cuda_runtime.h>
#include <cuda_fp16.h>
#include <stdint.h>

#define NPTS   65536
#define CCH    512
#define NH     8
#define PW     128
#define DHD    64
#define RPEN   31
#define PBND   15
#define SCALE  0.125f

// ---------------------------------------------------------------------------
// Static device scratch (fp16)
// ---------------------------------------------------------------------------
__device__ __half g_qhi[(size_t)NPTS * 1536];   // serialized qkv hi/lo
__device__ __half g_qlo[(size_t)NPTS * 1536];
__device__ __half g_fa [(size_t)NPTS * 512];    // feat[order], single fp16
__device__ __half g_aa [(size_t)NPTS * 512];    // attn-out (point order), single fp16
__device__ __half g_wqh[1536 * 512];
__device__ __half g_wql[1536 * 512];
__device__ __half g_wph[512 * 512];
__device__ __half g_wpl[512 * 512];

// ---------------------------------------------------------------------------
// PTX helpers (sm_100-legal)
// ---------------------------------------------------------------------------
__device__ __forceinline__ uint32_t smem_u32(const void* p) {
    uint32_t a;
    asm("{ .reg .u64 t; cvta.to.shared.u64 t, %1; cvt.u32.u64 %0, t; }"
        : "=r"(a) : "l"(p));
    return a;
}
__device__ __forceinline__ void cp16(uint32_t dst, const void* src) {
    asm volatile("cp.async.cg.shared.global [%0], [%1], 16;"
                 :: "r"(dst), "l"(src) : "memory");
}
__device__ __forceinline__ void cp_commit() {
    asm volatile("cp.async.commit_group;" ::: "memory");
}
template <int N>
__device__ __forceinline__ void cp_wait() {
    asm volatile("cp.async.wait_group %0;" :: "n"(N) : "memory");
}
__device__ __forceinline__ void ldm_x4(uint32_t* r, uint32_t addr) {
    asm volatile("ldmatrix.sync.aligned.m8n8.x4.shared.b16 {%0,%1,%2,%3}, [%4];"
                 : "=r"(r[0]), "=r"(r[1]), "=r"(r[2]), "=r"(r[3]) : "r"(addr));
}
__device__ __forceinline__ void ldm_x4_t(uint32_t* r, uint32_t addr) {
    asm volatile("ldmatrix.sync.aligned.m8n8.x4.trans.shared.b16 {%0,%1,%2,%3}, [%4];"
                 : "=r"(r[0]), "=r"(r[1]), "=r"(r[2]), "=r"(r[3]) : "r"(addr));
}
__device__ __forceinline__ void mma_f16(float* d, const uint32_t* a, const uint32_t* b) {
    asm volatile(
        "mma.sync.aligned.m16n8k16.row.col.f32.f16.f16.f32 "
        "{%0,%1,%2,%3}, {%4,%5,%6,%7}, {%8,%9}, {%0,%1,%2,%3};"
        : "+f"(d[0]), "+f"(d[1]), "+f"(d[2]), "+f"(d[3])
        : "r"(a[0]), "r"(a[1]), "r"(a[2]), "r"(a[3]), "r"(b[0]), "r"(b[1]));
}

// ---------------------------------------------------------------------------
// fp16 conversion kernels
// ---------------------------------------------------------------------------
__global__ void tohalf_gather_k(const float* __restrict__ src, const int* __restrict__ gidx,
                                __half* __restrict__ dst)
{
    int i = blockIdx.x * 256 + threadIdx.x;          // NPTS*128 float4 groups
    int m = i >> 7;
    int c = (i & 127) << 2;
    float4 v = *(const float4*)(src + (size_t)gidx[m] * 512 + c);
    __align__(8) __half hb[4];
    hb[0] = __float2half_rn(v.x); hb[1] = __float2half_rn(v.y);
    hb[2] = __float2half_rn(v.z); hb[3] = __float2half_rn(v.w);
    *(uint2*)(dst + (size_t)m * 512 + c) = *(uint2*)hb;
}

__global__ void split_plain_k(const float* __restrict__ src,
                              __half* __restrict__ hi, __half* __restrict__ lo, int n4)
{
    int i = blockIdx.x * 256 + threadIdx.x;
    if (i >= n4) return;
    float4 v = *(const float4*)(src + (size_t)i * 4);
    float xs[4] = {v.x, v.y, v.z, v.w};
    __align__(8) __half hb[4], lb[4];
#pragma unroll
    for (int j = 0; j < 4; j++) {
        hb[j] = __float2half_rn(xs[j]);
        lb[j] = __float2half_rn(xs[j] - __half2float(hb[j]));
    }
    size_t o = (size_t)i * 4;
    *(uint2*)(hi + o) = *(uint2*)hb;
    *(uint2*)(lo + o) = *(uint2*)lb;
}

// ---------------------------------------------------------------------------
// fp16 2-term GEMM: C[m][n] = sum_k A[m][k]*(Bh+Bl)[n][k] + bias[n]
// A single fp16; B split. K=512, tile 128x128, BK=32, 8 warps @ 64x32.
// Output: f32 (C) or fp16 hi/lo (Chi/Clo).
// ---------------------------------------------------------------------------
#define GK       512
#define BK       32
#define NCH      (GK / BK)
#define TROW_B   80             // 64B data + 16B pad
#define TILE_B   (128 * TROW_B)
#define STAGE_B  (3 * TILE_B)   // A, Bh, Bl
#define GSMEM    (2 * STAGE_B)  // 61440

__global__ __launch_bounds__(256, 2)
void gemm_f16x2(const __half* __restrict__ A,
                const __half* __restrict__ Bh, const __half* __restrict__ Bl,
                const float* __restrict__ bias, float* __restrict__ C,
                __half* __restrict__ Chi, __half* __restrict__ Clo, int Ntot)
{
    extern __shared__ __align__(128) char sm[];
    const uint32_t smb = smem_u32(sm);

    const int tid  = threadIdx.x;
    const int lane = tid & 31;
    const int warp = tid >> 5;
    const int wm   = warp >> 2;
    const int wn   = warp & 3;
    const int m0   = blockIdx.y * 128;
    const int n0   = blockIdx.x * 128;

    const __half* gsrc[3] = {
        A + (size_t)m0 * GK, Bh + (size_t)n0 * GK, Bl + (size_t)n0 * GK
    };

    auto load_stage = [&](int c) {
        const uint32_t sb = smb + (c & 1) * STAGE_B;
#pragma unroll
        for (int t = 0; t < 3; t++) {
            const __half* g = gsrc[t] + c * BK;
#pragma unroll
            for (int i = 0; i < 2; i++) {
                int idx = i * 256 + tid;
                int r = idx >> 2, s = idx & 3;
                cp16(sb + t * TILE_B + r * TROW_B + s * 16,
                     g + (size_t)r * GK + s * 8);
            }
        }
    };

    float acc[4][4][4];
#pragma unroll
    for (int i = 0; i < 4; i++)
#pragma unroll
        for (int j = 0; j < 4; j++)
#pragma unroll
            for (int e = 0; e < 4; e++) acc[i][j][e] = 0.f;

    const int arow  = lane & 15;
    const int acolb = (lane >> 4) * 16;
    const int brow  = (lane & 7) + (lane >> 4) * 8;
    const int bkb   = ((lane >> 3) & 1) * 16;

    load_stage(0);
    cp_commit();

    for (int c = 0; c < NCH; c++) {
        if (c + 1 < NCH) { load_stage(c + 1); cp_commit(); cp_wait<1>(); }
        else             { cp_wait<0>(); }
        __syncthreads();

        const uint32_t sb  = smb + (c & 1) * STAGE_B;
        const uint32_t sA  = sb;
        const uint32_t sBh = sb + TILE_B;
        const uint32_t sBl = sb + 2 * TILE_B;

#pragma unroll
        for (int ks = 0; ks < 2; ks++) {
            const int kb = ks * 32;
            uint32_t ah[4][4], bh[2][4], bl[2][4];
#pragma unroll
            for (int mi = 0; mi < 4; mi++)
                ldm_x4(ah[mi], sA + (wm * 64 + mi * 16 + arow) * TROW_B + kb + acolb);
#pragma unroll
            for (int jj = 0; jj < 2; jj++)
                ldm_x4(bh[jj], sBh + (wn * 32 + jj * 16 + brow) * TROW_B + kb + bkb);
#pragma unroll
            for (int mi = 0; mi < 4; mi++)
#pragma unroll
                for (int nj = 0; nj < 4; nj++)
                    mma_f16(acc[mi][nj], ah[mi], &bh[nj >> 1][(nj & 1) * 2]);
#pragma unroll
            for (int jj = 0; jj < 2; jj++)
                ldm_x4(bl[jj], sBl + (wn * 32 + jj * 16 + brow) * TROW_B + kb + bkb);
#pragma unroll
            for (int mi = 0; mi < 4; mi++)
#pragma unroll
                for (int nj = 0; nj < 4; nj++)
                    mma_f16(acc[mi][nj], ah[mi], &bl[nj >> 1][(nj & 1) * 2]);
        }
        if (c + 1 < NCH) __syncthreads();
    }

    const int gr = lane >> 2;
    const int gc = (lane & 3) * 2;
    float2 bv[4];
#pragma unroll
    for (int nj = 0; nj < 4; nj++)
        bv[nj] = *(const float2*)(bias + n0 + wn * 32 + nj * 8 + gc);

    if (Chi) {
#pragma unroll
        for (int mi = 0; mi < 4; mi++) {
            int rowa = m0 + wm * 64 + mi * 16 + gr;
#pragma unroll
            for (int nj = 0; nj < 4; nj++) {
                int col = n0 + wn * 32 + nj * 8 + gc;
                float v0 = acc[mi][nj][0] + bv[nj].x;
                float v1 = acc[mi][nj][1] + bv[nj].y;
                float v2 = acc[mi][nj][2] + bv[nj].x;
                float v3 = acc[mi][nj][3] + bv[nj].y;
                __half2 h01, h23, l01, l23;
                h01.x = __float2half_rn(v0); h01.y = __float2half_rn(v1);
                l01.x = __float2half_rn(v0 - __half2float(h01.x));
                l01.y = __float2half_rn(v1 - __half2float(h01.y));
                h23.x = __float2half_rn(v2); h23.y = __float2half_rn(v3);
                l23.x = __float2half_rn(v2 - __half2float(h23.x));
                l23.y = __float2half_rn(v3 - __half2float(h23.y));
                *(__half2*)(Chi + (size_t)rowa * Ntot + col)       = h01;
                *(__half2*)(Clo + (size_t)rowa * Ntot + col)       = l01;
                *(__half2*)(Chi + (size_t)(rowa + 8) * Ntot + col) = h23;
                *(__half2*)(Clo + (size_t)(rowa + 8) * Ntot + col) = l23;
            }
        }
    } else {
#pragma unroll
        for (int mi = 0; mi < 4; mi++) {
            int rowa = m0 + wm * 64 + mi * 16 + gr;
#pragma unroll
            for (int nj = 0; nj < 4; nj++) {
                int col = n0 + wn * 32 + nj * 8 + gc;
                float2 lo = make_float2(acc[mi][nj][0] + bv[nj].x, acc[mi][nj][1] + bv[nj].y);
                float2 hi = make_float2(acc[mi][nj][2] + bv[nj].x, acc[mi][nj][3] + bv[nj].y);
                *(float2*)(C + (size_t)rowa * Ntot + col)       = lo;
                *(float2*)(C + (size_t)(rowa + 8) * Ntot + col) = hi;
            }
        }
    }
}

// ---------------------------------------------------------------------------
// fp16 mma attention per (window, head). 3-term QK^T and PV (eps^2 accuracy).
// Output: single fp16, scattered through order.
// ---------------------------------------------------------------------------
#define ARS      144
#define AT_B     (128 * ARS)
#define OFF_QH   0
#define OFF_QL   (1 * AT_B)
#define OFF_KH   (2 * AT_B)
#define OFF_KL   (3 * AT_B)
#define OFF_VH   (4 * AT_B)
#define OFF_VL   (5 * AT_B)
#define OFF_RPE  (6 * AT_B)
#define OFF_GC   (OFF_RPE + 96 * 4)
#define OFF_ORD  (OFF_GC + 3 * 128 * 4)
#define ASMEM    (OFF_ORD + 128 * 4)

__global__ __launch_bounds__(256, 1)
void attn_mma(const __half* __restrict__ qhi, const __half* __restrict__ qlo,
              const int* __restrict__ order, const int* __restrict__ gcoord,
              const float* __restrict__ rpe, __half* __restrict__ oa)
{
    extern __shared__ __align__(128) char sm[];
    const uint32_t smb = smem_u32(sm);
    float* rpeS = (float*)(sm + OFF_RPE);
    int*   gcs  = (int*)(sm + OFF_GC);
    int*   ords = (int*)(sm + OFF_ORD);

    const int w    = blockIdx.x;
    const int hh   = blockIdx.y;
    const int tid  = threadIdx.x;
    const int lane = tid & 31;
    const int wid  = tid >> 5;
    const int wb   = w * PW;

    const __half* baseh = qhi + (size_t)wb * 1536 + hh * 64;
    const __half* basel = qlo + (size_t)wb * 1536 + hh * 64;
    const __half* srcp[6] = {
        baseh, basel, baseh + 512, basel + 512, baseh + 1024, basel + 1024
    };
#pragma unroll
    for (int m = 0; m < 6; m++) {
        uint32_t dstb = smb + m * AT_B;
#pragma unroll
        for (int i = 0; i < 4; i++) {
            int idx = i * 256 + tid;
            int r = idx >> 3, s = idx & 7;
            cp16(dstb + r * ARS + s * 16, srcp[m] + (size_t)r * 1536 + s * 8);
        }
    }
    cp_commit();

    for (int i = tid; i < 128; i += 256) {
        int g = order[wb + i];
        ords[i] = g;
        gcs[0 * 128 + i] = gcoord[g * 3 + 0];
        gcs[1 * 128 + i] = gcoord[g * 3 + 1];
        gcs[2 * 128 + i] = gcoord[g * 3 + 2];
    }
    for (int i = tid; i < 3 * RPEN; i += 256) rpeS[i] = rpe[i * NH + hh];
    cp_wait<0>();
    __syncthreads();

    const int w16   = wid * 16;
    const int arow  = lane & 15;
    const int acolb = (lane >> 4) * 16;
    const int brow  = (lane & 7) + (lane >> 4) * 8;
    const int bkb   = ((lane >> 3) & 1) * 16;

    // ---- S = QK^T : 3-term ----
    uint32_t qh4[4][4], ql4[4][4];
#pragma unroll
    for (int ks = 0; ks < 4; ks++) {
        ldm_x4(qh4[ks], smb + OFF_QH + (w16 + arow) * ARS + ks * 32 + acolb);
        ldm_x4(ql4[ks], smb + OFF_QL + (w16 + arow) * ARS + ks * 32 + acolb);
    }
    float s[16][4];
#pragma unroll
    for (int nj = 0; nj < 16; nj++)
#pragma unroll
        for (int e = 0; e < 4; e++) s[nj][e] = 0.f;

#pragma unroll
    for (int ks = 0; ks < 4; ks++) {
#pragma unroll
        for (int ng = 0; ng < 8; ng++) {
            uint32_t kh[4], kl[4];
            ldm_x4(kh, smb + OFF_KH + (ng * 16 + brow) * ARS + ks * 32 + bkb);
            ldm_x4(kl, smb + OFF_KL + (ng * 16 + brow) * ARS + ks * 32 + bkb);
            mma_f16(s[2 * ng],     qh4[ks], kh + 0);
            mma_f16(s[2 * ng + 1], qh4[ks], kh + 2);
            mma_f16(s[2 * ng],     qh4[ks], kl + 0);
            mma_f16(s[2 * ng + 1], qh4[ks], kl + 2);
            mma_f16(s[2 * ng],     ql4[ks], kh + 0);
            mma_f16(s[2 * ng + 1], ql4[ks], kh + 2);
        }
    }

    // ---- scale + RPE bias ----
    const int gr  = lane >> 2;
    const int gc2 = (lane & 3) * 2;
    const int r1  = w16 + gr, r2 = r1 + 8;
    const int qa0 = gcs[0 * 128 + r1], qa1 = gcs[1 * 128 + r1], qa2 = gcs[2 * 128 + r1];
    const int qb0 = gcs[0 * 128 + r2], qb1 = gcs[1 * 128 + r2], qb2 = gcs[2 * 128 + r2];

#pragma unroll
    for (int nj = 0; nj < 16; nj++) {
        int c0 = nj * 8 + gc2;
#pragma unroll
        for (int cc = 0; cc < 2; cc++) {
            int c  = c0 + cc;
            int k0 = gcs[0 * 128 + c], k1 = gcs[1 * 128 + c], k2 = gcs[2 * 128 + c];
            int ia0 = min(max(qa0 - k0, -PBND), PBND) + PBND;
            int ia1 = min(max(qa1 - k1, -PBND), PBND) + PBND + RPEN;
            int ia2 = min(max(qa2 - k2, -PBND), PBND) + PBND + 2 * RPEN;
            int ib0 = min(max(qb0 - k0, -PBND), PBND) + PBND;
            int ib1 = min(max(qb1 - k1, -PBND), PBND) + PBND + RPEN;
            int ib2 = min(max(qb2 - k2, -PBND), PBND) + PBND + 2 * RPEN;
            s[nj][cc]     = s[nj][cc]     * SCALE + rpeS[ia0] + rpeS[ia1] + rpeS[ia2];
            s[nj][2 + cc] = s[nj][2 + cc] * SCALE + rpeS[ib0] + rpeS[ib1] + rpeS[ib2];
        }
    }

    // ---- softmax ----
    float m1 = -1e30f, m2 = -1e30f;
#pragma unroll
    for (int nj = 0; nj < 16; nj++) {
        m1 = fmaxf(m1, fmaxf(s[nj][0], s[nj][1]));
        m2 = fmaxf(m2, fmaxf(s[nj][2], s[nj][3]));
    }
    m1 = fmaxf(m1, __shfl_xor_sync(0xffffffffu, m1, 1));
    m1 = fmaxf(m1, __shfl_xor_sync(0xffffffffu, m1, 2));
    m2 = fmaxf(m2, __shfl_xor_sync(0xffffffffu, m2, 1));
    m2 = fmaxf(m2, __shfl_xor_sync(0xffffffffu, m2, 2));
    float s1 = 0.f, s2 = 0.f;
#pragma unroll
    for (int nj = 0; nj < 16; nj++) {
        s[nj][0] = __expf(s[nj][0] - m1); s1 += s[nj][0];
        s[nj][1] = __expf(s[nj][1] - m1); s1 += s[nj][1];
        s[nj][2] = __expf(s[nj][2] - m2); s2 += s[nj][2];
        s[nj][3] = __expf(s[nj][3] - m2); s2 += s[nj][3];
    }
    s1 += __shfl_xor_sync(0xffffffffu, s1, 1);
    s1 += __shfl_xor_sync(0xffffffffu, s1, 2);
    s2 += __shfl_xor_sync(0xffffffffu, s2, 1);
    s2 += __shfl_xor_sync(0xffffffffu, s2, 2);
    float i1 = 1.0f / s1, i2 = 1.0f / s2;

    // ---- P -> fp16 hi/lo A-fragments ----
    uint32_t pha[8][4], pla[8][4];
#pragma unroll
    for (int kt = 0; kt < 8; kt++) {
#pragma unroll
        for (int half = 0; half < 2; half++) {
            int f = 2 * kt + half;
            float v0 = s[f][0] * i1, v1 = s[f][1] * i1;
            float v2 = s[f][2] * i2, v3 = s[f][3] * i2;
            __half2 h01, h23, l01, l23;
            h01.x = __float2half_rn(v0); h01.y = __float2half_rn(v1);
            l01.x = __float2half_rn(v0 - __half2float(h01.x));
            l01.y = __float2half_rn(v1 - __half2float(h01.y));
            h23.x = __float2half_rn(v2); h23.y = __float2half_rn(v3);
            l23.x = __float2half_rn(v2 - __half2float(h23.x));
            l23.y = __float2half_rn(v3 - __half2float(h23.y));
            pha[kt][0 + 2 * half] = *(uint32_t*)&h01;
            pha[kt][1 + 2 * half] = *(uint32_t*)&h23;
            pla[kt][0 + 2 * half] = *(uint32_t*)&l01;
            pla[kt][1 + 2 * half] = *(uint32_t*)&l23;
        }
    }

    // ---- O = P V : 3-term ----
    float o[8][4];
#pragma unroll
    for (int nj = 0; nj < 8; nj++)
#pragma unroll
        for (int e = 0; e < 4; e++) o[nj][e] = 0.f;

    const int vrow = ((lane >> 3) & 1) * 8 + (lane & 7);
    const int vcb  = (lane >> 4) * 16;
#pragma unroll
    for (int kt = 0; kt < 8; kt++) {
#pragma unroll
        for (int ng = 0; ng < 4; ng++) {
            uint32_t vh[4], vl[4];
            ldm_x4_t(vh, smb + OFF_VH + (kt * 16 + vrow) * ARS + ng * 32 + vcb);
            ldm_x4_t(vl, smb + OFF_VL + (kt * 16 + vrow) * ARS + ng * 32 + vcb);
            mma_f16(o[2 * ng],     pha[kt], vh + 0);
            mma_f16(o[2 * ng + 1], pha[kt], vh + 2);
            mma_f16(o[2 * ng],     pha[kt], vl + 0);
            mma_f16(o[2 * ng + 1], pha[kt], vl + 2);
            mma_f16(o[2 * ng],     pla[kt], vh + 0);
            mma_f16(o[2 * ng + 1], pla[kt], vh + 2);
        }
    }

    // ---- epilogue: single fp16, scatter through order ----
    const int d1 = ords[r1], d2 = ords[r2];
#pragma unroll
    for (int nj = 0; nj < 8; nj++) {
        int col = nj * 8 + gc2;
        __half2 h01, h23;
        h01.x = __float2half_rn(o[nj][0]); h01.y = __float2half_rn(o[nj][1]);
        h23.x = __float2half_rn(o[nj][2]); h23.y = __float2half_rn(o[nj][3]);
        *(__half2*)(oa + (size_t)d1 * 512 + hh * 64 + col) = h01;
        *(__half2*)(oa + (size_t)d2 * 512 + hh * 64 + col) = h23;
    }
}

// ---------------------------------------------------------------------------
extern "C" void kernel_launch(void* const* d_in, const int* in_sizes, int n_in,
                              void* d_out, int out_size)
{
    const float* feat    = (const float*)d_in[0];
    const float* w_qkv   = (const float*)d_in[1];
    const float* b_qkv   = (const float*)d_in[2];
    const float* w_proj  = (const float*)d_in[3];
    const float* b_proj  = (const float*)d_in[4];
    const float* rpe     = (const float*)d_in[5];
    const int*   gcoord  = (const int*)d_in[6];
    const int*   order   = (const int*)d_in[7];
    float*       out     = (float*)d_out;

    __half *qhi, *qlo, *fa, *aa, *wqh, *wql, *wph, *wpl;
    cudaGetSymbolAddress((void**)&qhi, g_qhi);
    cudaGetSymbolAddress((void**)&qlo, g_qlo);
    cudaGetSymbolAddress((void**)&fa,  g_fa);
    cudaGetSymbolAddress((void**)&aa,  g_aa);
    cudaGetSymbolAddress((void**)&wqh, g_wqh);
    cudaGetSymbolAddress((void**)&wql, g_wql);
    cudaGetSymbolAddress((void**)&wph, g_wph);
    cudaGetSymbolAddress((void**)&wpl, g_wpl);

    cudaFuncSetAttribute(gemm_f16x2, cudaFuncAttributeMaxDynamicSharedMemorySize, GSMEM);
    cudaFuncSetAttribute(attn_mma, cudaFuncAttributeMaxDynamicSharedMemorySize, ASMEM);

    // 1) fp16 conversions (A single; weights hi/lo split)
    tohalf_gather_k<<<NPTS * 128 / 256, 256>>>(feat, order, fa);
    split_plain_k<<<(1536 * 512 / 4) / 256, 256>>>(w_qkv, wqh, wql, 1536 * 512 / 4);
    split_plain_k<<<(512 * 512 / 4) / 256, 256>>>(w_proj, wph, wpl, 512 * 512 / 4);

    // 2) QKV projection (2-term) -> serialized qkv fp16 hi/lo (bias added)
    gemm_f16x2<<<dim3(1536 / 128, NPTS / 128), 256, GSMEM>>>(
        fa, wqh, wql, b_qkv, nullptr, qhi, qlo, 1536);

    // 3) fp16 mma attention (3-term); single-fp16 output scattered to point order
    attn_mma<<<dim3(NPTS / PW, NH), 256, ASMEM>>>(
        qhi, qlo, order, gcoord, rpe, aa);

    // 4) Output projection (2-term) -> f32 d_out
    gemm_f16x2<<<dim3(512 / 128, NPTS / 128), 256, GSMEM>>>(
        aa, wph, wpl, b_proj, out, nullptr, nullptr, 512);
}

// round 9
// speedup vs baseline: 1.7526x; 1.2942x over previous
#include <cuda_runtime.h>
#include <cuda_fp16.h>
#include <stdint.h>

#define NPTS   65536
#define CCH    512
#define NH     8
#define PW     128
#define DHD    64
#define RPEN   31
#define PBND   15
#define SCALE  0.125f

// ---------------------------------------------------------------------------
// Static device scratch (fp16)
// ---------------------------------------------------------------------------
__device__ __half g_qhi[(size_t)NPTS * 1536];   // serialized qkv hi/lo
__device__ __half g_qlo[(size_t)NPTS * 1536];
__device__ __half g_fa [(size_t)NPTS * 512];    // feat[order], single fp16
__device__ __half g_aa [(size_t)NPTS * 512];    // attn-out (point order), single fp16
__device__ __half g_wq [1536 * 512];            // w_qkv single fp16 (1-term GEMM1)
__device__ __half g_wph[512 * 512];             // w_proj hi/lo (2-term GEMM3)
__device__ __half g_wpl[512 * 512];

// ---------------------------------------------------------------------------
// PTX helpers (sm_100-legal)
// ---------------------------------------------------------------------------
__device__ __forceinline__ uint32_t smem_u32(const void* p) {
    uint32_t a;
    asm("{ .reg .u64 t; cvta.to.shared.u64 t, %1; cvt.u32.u64 %0, t; }"
        : "=r"(a) : "l"(p));
    return a;
}
__device__ __forceinline__ void cp16(uint32_t dst, const void* src) {
    asm volatile("cp.async.cg.shared.global [%0], [%1], 16;"
                 :: "r"(dst), "l"(src) : "memory");
}
__device__ __forceinline__ void cp_commit() {
    asm volatile("cp.async.commit_group;" ::: "memory");
}
template <int N>
__device__ __forceinline__ void cp_wait() {
    asm volatile("cp.async.wait_group %0;" :: "n"(N) : "memory");
}
__device__ __forceinline__ void ldm_x4(uint32_t* r, uint32_t addr) {
    asm volatile("ldmatrix.sync.aligned.m8n8.x4.shared.b16 {%0,%1,%2,%3}, [%4];"
                 : "=r"(r[0]), "=r"(r[1]), "=r"(r[2]), "=r"(r[3]) : "r"(addr));
}
__device__ __forceinline__ void ldm_x4_t(uint32_t* r, uint32_t addr) {
    asm volatile("ldmatrix.sync.aligned.m8n8.x4.trans.shared.b16 {%0,%1,%2,%3}, [%4];"
                 : "=r"(r[0]), "=r"(r[1]), "=r"(r[2]), "=r"(r[3]) : "r"(addr));
}
__device__ __forceinline__ void mma_f16(float* d, const uint32_t* a, const uint32_t* b) {
    asm volatile(
        "mma.sync.aligned.m16n8k16.row.col.f32.f16.f16.f32 "
        "{%0,%1,%2,%3}, {%4,%5,%6,%7}, {%8,%9}, {%0,%1,%2,%3};"
        : "+f"(d[0]), "+f"(d[1]), "+f"(d[2]), "+f"(d[3])
        : "r"(a[0]), "r"(a[1]), "r"(a[2]), "r"(a[3]), "r"(b[0]), "r"(b[1]));
}

// ---------------------------------------------------------------------------
// fp16 conversion kernels
// ---------------------------------------------------------------------------
__global__ void tohalf_gather_k(const float* __restrict__ src, const int* __restrict__ gidx,
                                __half* __restrict__ dst)
{
    int i = blockIdx.x * 256 + threadIdx.x;
    int m = i >> 7;
    int c = (i & 127) << 2;
    float4 v = *(const float4*)(src + (size_t)gidx[m] * 512 + c);
    __align__(8) __half hb[4];
    hb[0] = __float2half_rn(v.x); hb[1] = __float2half_rn(v.y);
    hb[2] = __float2half_rn(v.z); hb[3] = __float2half_rn(v.w);
    *(uint2*)(dst + (size_t)m * 512 + c) = *(uint2*)hb;
}

__global__ void tohalf_plain_k(const float* __restrict__ src, __half* __restrict__ dst, int n4)
{
    int i = blockIdx.x * 256 + threadIdx.x;
    if (i >= n4) return;
    float4 v = *(const float4*)(src + (size_t)i * 4);
    __align__(8) __half hb[4];
    hb[0] = __float2half_rn(v.x); hb[1] = __float2half_rn(v.y);
    hb[2] = __float2half_rn(v.z); hb[3] = __float2half_rn(v.w);
    *(uint2*)(dst + (size_t)i * 4) = *(uint2*)hb;
}

__global__ void split_plain_k(const float* __restrict__ src,
                              __half* __restrict__ hi, __half* __restrict__ lo, int n4)
{
    int i = blockIdx.x * 256 + threadIdx.x;
    if (i >= n4) return;
    float4 v = *(const float4*)(src + (size_t)i * 4);
    float xs[4] = {v.x, v.y, v.z, v.w};
    __align__(8) __half hb[4], lb[4];
#pragma unroll
    for (int j = 0; j < 4; j++) {
        hb[j] = __float2half_rn(xs[j]);
        lb[j] = __float2half_rn(xs[j] - __half2float(hb[j]));
    }
    size_t o = (size_t)i * 4;
    *(uint2*)(hi + o) = *(uint2*)hb;
    *(uint2*)(lo + o) = *(uint2*)lb;
}

// ---------------------------------------------------------------------------
// fp16 GEMM, NB B-terms (1 or 2): C[m][n] = sum_k A[m][k]*(B0(+B1))[n][k] + bias[n]
// K=512, tile 128x128, BK=64, 8 warps @ 64x32.
// Output: f32 (C) or fp16 hi/lo (Chi/Clo).
// ---------------------------------------------------------------------------
#define GK       512
#define BK       64
#define NCH      (GK / BK)       // 8
#define TROW_B   144             // 128B data + 16B pad
#define TILE_B   (128 * TROW_B)  // 18432

template <int NB>
__global__ __launch_bounds__(256, 2)
void gemm_f16(const __half* __restrict__ A,
              const __half* __restrict__ B0, const __half* __restrict__ B1,
              const float* __restrict__ bias, float* __restrict__ C,
              __half* __restrict__ Chi, __half* __restrict__ Clo, int Ntot)
{
    constexpr int NT      = 1 + NB;          // tiles per stage
    constexpr int STAGE_B = NT * TILE_B;

    extern __shared__ __align__(128) char sm[];
    const uint32_t smb = smem_u32(sm);

    const int tid  = threadIdx.x;
    const int lane = tid & 31;
    const int warp = tid >> 5;
    const int wm   = warp >> 2;
    const int wn   = warp & 3;
    const int m0   = blockIdx.y * 128;
    const int n0   = blockIdx.x * 128;

    const __half* gsrc[3];
    gsrc[0] = A + (size_t)m0 * GK;
    gsrc[1] = B0 + (size_t)n0 * GK;
    if (NB == 2) gsrc[2] = B1 + (size_t)n0 * GK;

    auto load_stage = [&](int c) {
        const uint32_t sb = smb + (c & 1) * STAGE_B;
#pragma unroll
        for (int t = 0; t < NT; t++) {
            const __half* g = gsrc[t] + c * BK;
#pragma unroll
            for (int i = 0; i < 4; i++) {
                int idx = i * 256 + tid;         // 0..1023
                int r = idx >> 3, s = idx & 7;   // row, 16B segment
                cp16(sb + t * TILE_B + r * TROW_B + s * 16,
                     g + (size_t)r * GK + s * 8);
            }
        }
    };

    float acc[4][4][4];
#pragma unroll
    for (int i = 0; i < 4; i++)
#pragma unroll
        for (int j = 0; j < 4; j++)
#pragma unroll
            for (int e = 0; e < 4; e++) acc[i][j][e] = 0.f;

    const int arow  = lane & 15;
    const int acolb = (lane >> 4) * 16;
    const int brow  = (lane & 7) + (lane >> 4) * 8;
    const int bkb   = ((lane >> 3) & 1) * 16;

    load_stage(0);
    cp_commit();

    for (int c = 0; c < NCH; c++) {
        if (c + 1 < NCH) { load_stage(c + 1); cp_commit(); cp_wait<1>(); }
        else             { cp_wait<0>(); }
        __syncthreads();

        const uint32_t sb  = smb + (c & 1) * STAGE_B;
        const uint32_t sA  = sb;
        const uint32_t sB0 = sb + TILE_B;
        const uint32_t sB1 = sb + 2 * TILE_B;

#pragma unroll
        for (int ks = 0; ks < 4; ks++) {         // 4 k-steps of 16 within BK=64
            const int kb = ks * 32;
            uint32_t ah[4][4], b0[2][4], b1[2][4];
#pragma unroll
            for (int mi = 0; mi < 4; mi++)
                ldm_x4(ah[mi], sA + (wm * 64 + mi * 16 + arow) * TROW_B + kb + acolb);
#pragma unroll
            for (int jj = 0; jj < 2; jj++)
                ldm_x4(b0[jj], sB0 + (wn * 32 + jj * 16 + brow) * TROW_B + kb + bkb);
#pragma unroll
            for (int mi = 0; mi < 4; mi++)
#pragma unroll
                for (int nj = 0; nj < 4; nj++)
                    mma_f16(acc[mi][nj], ah[mi], &b0[nj >> 1][(nj & 1) * 2]);
            if (NB == 2) {
#pragma unroll
                for (int jj = 0; jj < 2; jj++)
                    ldm_x4(b1[jj], sB1 + (wn * 32 + jj * 16 + brow) * TROW_B + kb + bkb);
#pragma unroll
                for (int mi = 0; mi < 4; mi++)
#pragma unroll
                    for (int nj = 0; nj < 4; nj++)
                        mma_f16(acc[mi][nj], ah[mi], &b1[nj >> 1][(nj & 1) * 2]);
            }
        }
        if (c + 1 < NCH) __syncthreads();
    }

    const int gr = lane >> 2;
    const int gc = (lane & 3) * 2;
    float2 bv[4];
#pragma unroll
    for (int nj = 0; nj < 4; nj++)
        bv[nj] = *(const float2*)(bias + n0 + wn * 32 + nj * 8 + gc);

    if (Chi) {
#pragma unroll
        for (int mi = 0; mi < 4; mi++) {
            int rowa = m0 + wm * 64 + mi * 16 + gr;
#pragma unroll
            for (int nj = 0; nj < 4; nj++) {
                int col = n0 + wn * 32 + nj * 8 + gc;
                float v0 = acc[mi][nj][0] + bv[nj].x;
                float v1 = acc[mi][nj][1] + bv[nj].y;
                float v2 = acc[mi][nj][2] + bv[nj].x;
                float v3 = acc[mi][nj][3] + bv[nj].y;
                __half2 h01, h23, l01, l23;
                h01.x = __float2half_rn(v0); h01.y = __float2half_rn(v1);
                l01.x = __float2half_rn(v0 - __half2float(h01.x));
                l01.y = __float2half_rn(v1 - __half2float(h01.y));
                h23.x = __float2half_rn(v2); h23.y = __float2half_rn(v3);
                l23.x = __float2half_rn(v2 - __half2float(h23.x));
                l23.y = __float2half_rn(v3 - __half2float(h23.y));
                *(__half2*)(Chi + (size_t)rowa * Ntot + col)       = h01;
                *(__half2*)(Clo + (size_t)rowa * Ntot + col)       = l01;
                *(__half2*)(Chi + (size_t)(rowa + 8) * Ntot + col) = h23;
                *(__half2*)(Clo + (size_t)(rowa + 8) * Ntot + col) = l23;
            }
        }
    } else {
#pragma unroll
        for (int mi = 0; mi < 4; mi++) {
            int rowa = m0 + wm * 64 + mi * 16 + gr;
#pragma unroll
            for (int nj = 0; nj < 4; nj++) {
                int col = n0 + wn * 32 + nj * 8 + gc;
                float2 lo = make_float2(acc[mi][nj][0] + bv[nj].x, acc[mi][nj][1] + bv[nj].y);
                float2 hi = make_float2(acc[mi][nj][2] + bv[nj].x, acc[mi][nj][3] + bv[nj].y);
                *(float2*)(C + (size_t)rowa * Ntot + col)       = lo;
                *(float2*)(C + (size_t)(rowa + 8) * Ntot + col) = hi;
            }
        }
    }
}

#define GSMEM1 (2 * 2 * TILE_B)   // 1-term: A + B0, double buffered
#define GSMEM2 (2 * 3 * TILE_B)   // 2-term: A + B0 + B1

// ---------------------------------------------------------------------------
// fp16 mma attention per (window, head). 3-term QK^T and PV (eps^2 accuracy).
// Output: single fp16, scattered through order.
// ---------------------------------------------------------------------------
#define ARS      144
#define AT_B     (128 * ARS)
#define OFF_QH   0
#define OFF_QL   (1 * AT_B)
#define OFF_KH   (2 * AT_B)
#define OFF_KL   (3 * AT_B)
#define OFF_VH   (4 * AT_B)
#define OFF_VL   (5 * AT_B)
#define OFF_RPE  (6 * AT_B)
#define OFF_GC   (OFF_RPE + 96 * 4)
#define OFF_ORD  (OFF_GC + 3 * 128 * 4)
#define ASMEM    (OFF_ORD + 128 * 4)

__global__ __launch_bounds__(256, 1)
void attn_mma(const __half* __restrict__ qhi, const __half* __restrict__ qlo,
              const int* __restrict__ order, const int* __restrict__ gcoord,
              const float* __restrict__ rpe, __half* __restrict__ oa)
{
    extern __shared__ __align__(128) char sm[];
    const uint32_t smb = smem_u32(sm);
    float* rpeS = (float*)(sm + OFF_RPE);
    int*   gcs  = (int*)(sm + OFF_GC);
    int*   ords = (int*)(sm + OFF_ORD);

    const int w    = blockIdx.x;
    const int hh   = blockIdx.y;
    const int tid  = threadIdx.x;
    const int lane = tid & 31;
    const int wid  = tid >> 5;
    const int wb   = w * PW;

    const __half* baseh = qhi + (size_t)wb * 1536 + hh * 64;
    const __half* basel = qlo + (size_t)wb * 1536 + hh * 64;
    const __half* srcp[6] = {
        baseh, basel, baseh + 512, basel + 512, baseh + 1024, basel + 1024
    };
#pragma unroll
    for (int m = 0; m < 6; m++) {
        uint32_t dstb = smb + m * AT_B;
#pragma unroll
        for (int i = 0; i < 4; i++) {
            int idx = i * 256 + tid;
            int r = idx >> 3, s = idx & 7;
            cp16(dstb + r * ARS + s * 16, srcp[m] + (size_t)r * 1536 + s * 8);
        }
    }
    cp_commit();

    for (int i = tid; i < 128; i += 256) {
        int g = order[wb + i];
        ords[i] = g;
        gcs[0 * 128 + i] = gcoord[g * 3 + 0];
        gcs[1 * 128 + i] = gcoord[g * 3 + 1];
        gcs[2 * 128 + i] = gcoord[g * 3 + 2];
    }
    for (int i = tid; i < 3 * RPEN; i += 256) rpeS[i] = rpe[i * NH + hh];
    cp_wait<0>();
    __syncthreads();

    const int w16   = wid * 16;
    const int arow  = lane & 15;
    const int acolb = (lane >> 4) * 16;
    const int brow  = (lane & 7) + (lane >> 4) * 8;
    const int bkb   = ((lane >> 3) & 1) * 16;

    // ---- S = QK^T : 3-term ----
    uint32_t qh4[4][4], ql4[4][4];
#pragma unroll
    for (int ks = 0; ks < 4; ks++) {
        ldm_x4(qh4[ks], smb + OFF_QH + (w16 + arow) * ARS + ks * 32 + acolb);
        ldm_x4(ql4[ks], smb + OFF_QL + (w16 + arow) * ARS + ks * 32 + acolb);
    }
    float s[16][4];
#pragma unroll
    for (int nj = 0; nj < 16; nj++)
#pragma unroll
        for (int e = 0; e < 4; e++) s[nj][e] = 0.f;

#pragma unroll
    for (int ks = 0; ks < 4; ks++) {
#pragma unroll
        for (int ng = 0; ng < 8; ng++) {
            uint32_t kh[4], kl[4];
            ldm_x4(kh, smb + OFF_KH + (ng * 16 + brow) * ARS + ks * 32 + bkb);
            ldm_x4(kl, smb + OFF_KL + (ng * 16 + brow) * ARS + ks * 32 + bkb);
            mma_f16(s[2 * ng],     qh4[ks], kh + 0);
            mma_f16(s[2 * ng + 1], qh4[ks], kh + 2);
            mma_f16(s[2 * ng],     qh4[ks], kl + 0);
            mma_f16(s[2 * ng + 1], qh4[ks], kl + 2);
            mma_f16(s[2 * ng],     ql4[ks], kh + 0);
            mma_f16(s[2 * ng + 1], ql4[ks], kh + 2);
        }
    }

    // ---- scale + RPE bias ----
    const int gr  = lane >> 2;
    const int gc2 = (lane & 3) * 2;
    const int r1  = w16 + gr, r2 = r1 + 8;
    const int qa0 = gcs[0 * 128 + r1], qa1 = gcs[1 * 128 + r1], qa2 = gcs[2 * 128 + r1];
    const int qb0 = gcs[0 * 128 + r2], qb1 = gcs[1 * 128 + r2], qb2 = gcs[2 * 128 + r2];

#pragma unroll
    for (int nj = 0; nj < 16; nj++) {
        int c0 = nj * 8 + gc2;
#pragma unroll
        for (int cc = 0; cc < 2; cc++) {
            int c  = c0 + cc;
            int k0 = gcs[0 * 128 + c], k1 = gcs[1 * 128 + c], k2 = gcs[2 * 128 + c];
            int ia0 = min(max(qa0 - k0, -PBND), PBND) + PBND;
            int ia1 = min(max(qa1 - k1, -PBND), PBND) + PBND + RPEN;
            int ia2 = min(max(qa2 - k2, -PBND), PBND) + PBND + 2 * RPEN;
            int ib0 = min(max(qb0 - k0, -PBND), PBND) + PBND;
            int ib1 = min(max(qb1 - k1, -PBND), PBND) + PBND + RPEN;
            int ib2 = min(max(qb2 - k2, -PBND), PBND) + PBND + 2 * RPEN;
            s[nj][cc]     = s[nj][cc]     * SCALE + rpeS[ia0] + rpeS[ia1] + rpeS[ia2];
            s[nj][2 + cc] = s[nj][2 + cc] * SCALE + rpeS[ib0] + rpeS[ib1] + rpeS[ib2];
        }
    }

    // ---- softmax ----
    float m1 = -1e30f, m2 = -1e30f;
#pragma unroll
    for (int nj = 0; nj < 16; nj++) {
        m1 = fmaxf(m1, fmaxf(s[nj][0], s[nj][1]));
        m2 = fmaxf(m2, fmaxf(s[nj][2], s[nj][3]));
    }
    m1 = fmaxf(m1, __shfl_xor_sync(0xffffffffu, m1, 1));
    m1 = fmaxf(m1, __shfl_xor_sync(0xffffffffu, m1, 2));
    m2 = fmaxf(m2, __shfl_xor_sync(0xffffffffu, m2, 1));
    m2 = fmaxf(m2, __shfl_xor_sync(0xffffffffu, m2, 2));
    float s1 = 0.f, s2 = 0.f;
#pragma unroll
    for (int nj = 0; nj < 16; nj++) {
        s[nj][0] = __expf(s[nj][0] - m1); s1 += s[nj][0];
        s[nj][1] = __expf(s[nj][1] - m1); s1 += s[nj][1];
        s[nj][2] = __expf(s[nj][2] - m2); s2 += s[nj][2];
        s[nj][3] = __expf(s[nj][3] - m2); s2 += s[nj][3];
    }
    s1 += __shfl_xor_sync(0xffffffffu, s1, 1);
    s1 += __shfl_xor_sync(0xffffffffu, s1, 2);
    s2 += __shfl_xor_sync(0xffffffffu, s2, 1);
    s2 += __shfl_xor_sync(0xffffffffu, s2, 2);
    float i1 = 1.0f / s1, i2 = 1.0f / s2;

    // ---- P -> fp16 hi/lo A-fragments ----
    uint32_t pha[8][4], pla[8][4];
#pragma unroll
    for (int kt = 0; kt < 8; kt++) {
#pragma unroll
        for (int half = 0; half < 2; half++) {
            int f = 2 * kt + half;
            float v0 = s[f][0] * i1, v1 = s[f][1] * i1;
            float v2 = s[f][2] * i2, v3 = s[f][3] * i2;
            __half2 h01, h23, l01, l23;
            h01.x = __float2half_rn(v0); h01.y = __float2half_rn(v1);
            l01.x = __float2half_rn(v0 - __half2float(h01.x));
            l01.y = __float2half_rn(v1 - __half2float(h01.y));
            h23.x = __float2half_rn(v2); h23.y = __float2half_rn(v3);
            l23.x = __float2half_rn(v2 - __half2float(h23.x));
            l23.y = __float2half_rn(v3 - __half2float(h23.y));
            pha[kt][0 + 2 * half] = *(uint32_t*)&h01;
            pha[kt][1 + 2 * half] = *(uint32_t*)&h23;
            pla[kt][0 + 2 * half] = *(uint32_t*)&l01;
            pla[kt][1 + 2 * half] = *(uint32_t*)&l23;
        }
    }

    // ---- O = P V : 3-term ----
    float o[8][4];
#pragma unroll
    for (int nj = 0; nj < 8; nj++)
#pragma unroll
        for (int e = 0; e < 4; e++) o[nj][e] = 0.f;

    const int vrow = ((lane >> 3) & 1) * 8 + (lane & 7);
    const int vcb  = (lane >> 4) * 16;
#pragma unroll
    for (int kt = 0; kt < 8; kt++) {
#pragma unroll
        for (int ng = 0; ng < 4; ng++) {
            uint32_t vh[4], vl[4];
            ldm_x4_t(vh, smb + OFF_VH + (kt * 16 + vrow) * ARS + ng * 32 + vcb);
            ldm_x4_t(vl, smb + OFF_VL + (kt * 16 + vrow) * ARS + ng * 32 + vcb);
            mma_f16(o[2 * ng],     pha[kt], vh + 0);
            mma_f16(o[2 * ng + 1], pha[kt], vh + 2);
            mma_f16(o[2 * ng],     pha[kt], vl + 0);
            mma_f16(o[2 * ng + 1], pha[kt], vl + 2);
            mma_f16(o[2 * ng],     pla[kt], vh + 0);
            mma_f16(o[2 * ng + 1], pla[kt], vh + 2);
        }
    }

    // ---- epilogue: single fp16, scatter through order ----
    const int d1 = ords[r1], d2 = ords[r2];
#pragma unroll
    for (int nj = 0; nj < 8; nj++) {
        int col = nj * 8 + gc2;
        __half2 h01, h23;
        h01.x = __float2half_rn(o[nj][0]); h01.y = __float2half_rn(o[nj][1]);
        h23.x = __float2half_rn(o[nj][2]); h23.y = __float2half_rn(o[nj][3]);
        *(__half2*)(oa + (size_t)d1 * 512 + hh * 64 + col) = h01;
        *(__half2*)(oa + (size_t)d2 * 512 + hh * 64 + col) = h23;
    }
}

// ---------------------------------------------------------------------------
extern "C" void kernel_launch(void* const* d_in, const int* in_sizes, int n_in,
                              void* d_out, int out_size)
{
    const float* feat    = (const float*)d_in[0];
    const float* w_qkv   = (const float*)d_in[1];
    const float* b_qkv   = (const float*)d_in[2];
    const float* w_proj  = (const float*)d_in[3];
    const float* b_proj  = (const float*)d_in[4];
    const float* rpe     = (const float*)d_in[5];
    const int*   gcoord  = (const int*)d_in[6];
    const int*   order   = (const int*)d_in[7];
    float*       out     = (float*)d_out;

    __half *qhi, *qlo, *fa, *aa, *wq, *wph, *wpl;
    cudaGetSymbolAddress((void**)&qhi, g_qhi);
    cudaGetSymbolAddress((void**)&qlo, g_qlo);
    cudaGetSymbolAddress((void**)&fa,  g_fa);
    cudaGetSymbolAddress((void**)&aa,  g_aa);
    cudaGetSymbolAddress((void**)&wq,  g_wq);
    cudaGetSymbolAddress((void**)&wph, g_wph);
    cudaGetSymbolAddress((void**)&wpl, g_wpl);

    cudaFuncSetAttribute(gemm_f16<1>, cudaFuncAttributeMaxDynamicSharedMemorySize, GSMEM1);
    cudaFuncSetAttribute(gemm_f16<2>, cudaFuncAttributeMaxDynamicSharedMemorySize, GSMEM2);
    cudaFuncSetAttribute(attn_mma, cudaFuncAttributeMaxDynamicSharedMemorySize, ASMEM);

    // 1) fp16 conversions
    tohalf_gather_k<<<NPTS * 128 / 256, 256>>>(feat, order, fa);
    tohalf_plain_k<<<(1536 * 512 / 4) / 256, 256>>>(w_qkv, wq, 1536 * 512 / 4);
    split_plain_k<<<(512 * 512 / 4) / 256, 256>>>(w_proj, wph, wpl, 512 * 512 / 4);

    // 2) QKV projection (1-term fp16) -> serialized qkv fp16 hi/lo (bias added)
    gemm_f16<1><<<dim3(1536 / 128, NPTS / 128), 256, GSMEM1>>>(
        fa, wq, nullptr, b_qkv, nullptr, qhi, qlo, 1536);

    // 3) fp16 mma attention (3-term); single-fp16 output scattered to point order
    attn_mma<<<dim3(NPTS / PW, NH), 256, ASMEM>>>(
        qhi, qlo, order, gcoord, rpe, aa);

    // 4) Output projection (2-term) -> f32 d_out
    gemm_f16<2><<<dim3(512 / 128, NPTS / 128), 256, GSMEM2>>>(
        aa, wph, wpl, b_proj, out, nullptr, nullptr, 512);
}

// round 10
// speedup vs baseline: 2.3055x; 1.3155x over previous
#include <cuda_runtime.h>
#include <cuda_fp16.h>
#include <stdint.h>

#define NPTS   65536
#define CCH    512
#define NH     8
#define PW     128
#define DHD    64
#define RPEN   31
#define PBND   15
#define SCALE  0.125f

// ---------------------------------------------------------------------------
// Static device scratch (fp16)
// ---------------------------------------------------------------------------
__device__ __half g_qkv[(size_t)NPTS * 1536];   // serialized qkv, single fp16
__device__ __half g_fa [(size_t)NPTS * 512];    // feat[order], single fp16
__device__ __half g_aa [(size_t)NPTS * 512];    // attn-out (point order), single fp16
__device__ __half g_wq [1536 * 512];            // w_qkv single fp16
__device__ __half g_wph[512 * 512];             // w_proj hi/lo (2-term GEMM3)
__device__ __half g_wpl[512 * 512];

// ---------------------------------------------------------------------------
// PTX helpers (sm_100-legal)
// ---------------------------------------------------------------------------
__device__ __forceinline__ uint32_t smem_u32(const void* p) {
    uint32_t a;
    asm("{ .reg .u64 t; cvta.to.shared.u64 t, %1; cvt.u32.u64 %0, t; }"
        : "=r"(a) : "l"(p));
    return a;
}
__device__ __forceinline__ void cp16(uint32_t dst, const void* src) {
    asm volatile("cp.async.cg.shared.global [%0], [%1], 16;"
                 :: "r"(dst), "l"(src) : "memory");
}
__device__ __forceinline__ void cp_commit() {
    asm volatile("cp.async.commit_group;" ::: "memory");
}
template <int N>
__device__ __forceinline__ void cp_wait() {
    asm volatile("cp.async.wait_group %0;" :: "n"(N) : "memory");
}
__device__ __forceinline__ void ldm_x4(uint32_t* r, uint32_t addr) {
    asm volatile("ldmatrix.sync.aligned.m8n8.x4.shared.b16 {%0,%1,%2,%3}, [%4];"
                 : "=r"(r[0]), "=r"(r[1]), "=r"(r[2]), "=r"(r[3]) : "r"(addr));
}
__device__ __forceinline__ void ldm_x4_t(uint32_t* r, uint32_t addr) {
    asm volatile("ldmatrix.sync.aligned.m8n8.x4.trans.shared.b16 {%0,%1,%2,%3}, [%4];"
                 : "=r"(r[0]), "=r"(r[1]), "=r"(r[2]), "=r"(r[3]) : "r"(addr));
}
__device__ __forceinline__ void mma_f16(float* d, const uint32_t* a, const uint32_t* b) {
    asm volatile(
        "mma.sync.aligned.m16n8k16.row.col.f32.f16.f16.f32 "
        "{%0,%1,%2,%3}, {%4,%5,%6,%7}, {%8,%9}, {%0,%1,%2,%3};"
        : "+f"(d[0]), "+f"(d[1]), "+f"(d[2]), "+f"(d[3])
        : "r"(a[0]), "r"(a[1]), "r"(a[2]), "r"(a[3]), "r"(b[0]), "r"(b[1]));
}

// ---------------------------------------------------------------------------
// fp16 conversion kernels
// ---------------------------------------------------------------------------
__global__ void tohalf_gather_k(const float* __restrict__ src, const int* __restrict__ gidx,
                                __half* __restrict__ dst)
{
    int i = blockIdx.x * 256 + threadIdx.x;
    int m = i >> 7;
    int c = (i & 127) << 2;
    float4 v = *(const float4*)(src + (size_t)gidx[m] * 512 + c);
    __align__(8) __half hb[4];
    hb[0] = __float2half_rn(v.x); hb[1] = __float2half_rn(v.y);
    hb[2] = __float2half_rn(v.z); hb[3] = __float2half_rn(v.w);
    *(uint2*)(dst + (size_t)m * 512 + c) = *(uint2*)hb;
}

__global__ void tohalf_plain_k(const float* __restrict__ src, __half* __restrict__ dst, int n4)
{
    int i = blockIdx.x * 256 + threadIdx.x;
    if (i >= n4) return;
    float4 v = *(const float4*)(src + (size_t)i * 4);
    __align__(8) __half hb[4];
    hb[0] = __float2half_rn(v.x); hb[1] = __float2half_rn(v.y);
    hb[2] = __float2half_rn(v.z); hb[3] = __float2half_rn(v.w);
    *(uint2*)(dst + (size_t)i * 4) = *(uint2*)hb;
}

__global__ void split_plain_k(const float* __restrict__ src,
                              __half* __restrict__ hi, __half* __restrict__ lo, int n4)
{
    int i = blockIdx.x * 256 + threadIdx.x;
    if (i >= n4) return;
    float4 v = *(const float4*)(src + (size_t)i * 4);
    float xs[4] = {v.x, v.y, v.z, v.w};
    __align__(8) __half hb[4], lb[4];
#pragma unroll
    for (int j = 0; j < 4; j++) {
        hb[j] = __float2half_rn(xs[j]);
        lb[j] = __float2half_rn(xs[j] - __half2float(hb[j]));
    }
    size_t o = (size_t)i * 4;
    *(uint2*)(hi + o) = *(uint2*)hb;
    *(uint2*)(lo + o) = *(uint2*)lb;
}

// ---------------------------------------------------------------------------
// fp16 GEMM, NB B-terms (1 or 2): C[m][n] = sum_k A[m][k]*(B0(+B1))[n][k] + bias[n]
// K=512, tile 128x128, BK=64, 8 warps @ 64x32.
// Output: f32 (C) or single fp16 (Chalf).
// ---------------------------------------------------------------------------
#define GK       512
#define BK       64
#define NCH      (GK / BK)       // 8
#define TROW_B   144             // 128B data + 16B pad
#define TILE_B   (128 * TROW_B)  // 18432

template <int NB>
__global__ __launch_bounds__(256, 2)
void gemm_f16(const __half* __restrict__ A,
              const __half* __restrict__ B0, const __half* __restrict__ B1,
              const float* __restrict__ bias, float* __restrict__ C,
              __half* __restrict__ Chalf, int Ntot)
{
    constexpr int NT      = 1 + NB;
    constexpr int STAGE_B = NT * TILE_B;

    extern __shared__ __align__(128) char sm[];
    const uint32_t smb = smem_u32(sm);

    const int tid  = threadIdx.x;
    const int lane = tid & 31;
    const int warp = tid >> 5;
    const int wm   = warp >> 2;
    const int wn   = warp & 3;
    const int m0   = blockIdx.y * 128;
    const int n0   = blockIdx.x * 128;

    const __half* gsrc[3];
    gsrc[0] = A + (size_t)m0 * GK;
    gsrc[1] = B0 + (size_t)n0 * GK;
    if (NB == 2) gsrc[2] = B1 + (size_t)n0 * GK;

    auto load_stage = [&](int c) {
        const uint32_t sb = smb + (c & 1) * STAGE_B;
#pragma unroll
        for (int t = 0; t < NT; t++) {
            const __half* g = gsrc[t] + c * BK;
#pragma unroll
            for (int i = 0; i < 4; i++) {
                int idx = i * 256 + tid;
                int r = idx >> 3, s = idx & 7;
                cp16(sb + t * TILE_B + r * TROW_B + s * 16,
                     g + (size_t)r * GK + s * 8);
            }
        }
    };

    float acc[4][4][4];
#pragma unroll
    for (int i = 0; i < 4; i++)
#pragma unroll
        for (int j = 0; j < 4; j++)
#pragma unroll
            for (int e = 0; e < 4; e++) acc[i][j][e] = 0.f;

    const int arow  = lane & 15;
    const int acolb = (lane >> 4) * 16;
    const int brow  = (lane & 7) + (lane >> 4) * 8;
    const int bkb   = ((lane >> 3) & 1) * 16;

    load_stage(0);
    cp_commit();

    for (int c = 0; c < NCH; c++) {
        if (c + 1 < NCH) { load_stage(c + 1); cp_commit(); cp_wait<1>(); }
        else             { cp_wait<0>(); }
        __syncthreads();

        const uint32_t sb  = smb + (c & 1) * STAGE_B;
        const uint32_t sA  = sb;
        const uint32_t sB0 = sb + TILE_B;
        const uint32_t sB1 = sb + 2 * TILE_B;

#pragma unroll
        for (int ks = 0; ks < 4; ks++) {
            const int kb = ks * 32;
            uint32_t ah[4][4], b0[2][4], b1[2][4];
#pragma unroll
            for (int mi = 0; mi < 4; mi++)
                ldm_x4(ah[mi], sA + (wm * 64 + mi * 16 + arow) * TROW_B + kb + acolb);
#pragma unroll
            for (int jj = 0; jj < 2; jj++)
                ldm_x4(b0[jj], sB0 + (wn * 32 + jj * 16 + brow) * TROW_B + kb + bkb);
#pragma unroll
            for (int mi = 0; mi < 4; mi++)
#pragma unroll
                for (int nj = 0; nj < 4; nj++)
                    mma_f16(acc[mi][nj], ah[mi], &b0[nj >> 1][(nj & 1) * 2]);
            if (NB == 2) {
#pragma unroll
                for (int jj = 0; jj < 2; jj++)
                    ldm_x4(b1[jj], sB1 + (wn * 32 + jj * 16 + brow) * TROW_B + kb + bkb);
#pragma unroll
                for (int mi = 0; mi < 4; mi++)
#pragma unroll
                    for (int nj = 0; nj < 4; nj++)
                        mma_f16(acc[mi][nj], ah[mi], &b1[nj >> 1][(nj & 1) * 2]);
            }
        }
        if (c + 1 < NCH) __syncthreads();
    }

    const int gr = lane >> 2;
    const int gc = (lane & 3) * 2;
    float2 bv[4];
#pragma unroll
    for (int nj = 0; nj < 4; nj++)
        bv[nj] = *(const float2*)(bias + n0 + wn * 32 + nj * 8 + gc);

    if (Chalf) {
#pragma unroll
        for (int mi = 0; mi < 4; mi++) {
            int rowa = m0 + wm * 64 + mi * 16 + gr;
#pragma unroll
            for (int nj = 0; nj < 4; nj++) {
                int col = n0 + wn * 32 + nj * 8 + gc;
                __half2 h01, h23;
                h01.x = __float2half_rn(acc[mi][nj][0] + bv[nj].x);
                h01.y = __float2half_rn(acc[mi][nj][1] + bv[nj].y);
                h23.x = __float2half_rn(acc[mi][nj][2] + bv[nj].x);
                h23.y = __float2half_rn(acc[mi][nj][3] + bv[nj].y);
                *(__half2*)(Chalf + (size_t)rowa * Ntot + col)       = h01;
                *(__half2*)(Chalf + (size_t)(rowa + 8) * Ntot + col) = h23;
            }
        }
    } else {
#pragma unroll
        for (int mi = 0; mi < 4; mi++) {
            int rowa = m0 + wm * 64 + mi * 16 + gr;
#pragma unroll
            for (int nj = 0; nj < 4; nj++) {
                int col = n0 + wn * 32 + nj * 8 + gc;
                float2 lo = make_float2(acc[mi][nj][0] + bv[nj].x, acc[mi][nj][1] + bv[nj].y);
                float2 hi = make_float2(acc[mi][nj][2] + bv[nj].x, acc[mi][nj][3] + bv[nj].y);
                *(float2*)(C + (size_t)rowa * Ntot + col)       = lo;
                *(float2*)(C + (size_t)(rowa + 8) * Ntot + col) = hi;
            }
        }
    }
}

#define GSMEM1 (2 * 2 * TILE_B)
#define GSMEM2 (2 * 3 * TILE_B)

// ---------------------------------------------------------------------------
// fp16 mma attention per (window, head). Single-term QK^T and PV.
// smem: q | k | v tiles + rpe + gc + ord. 2 CTAs/SM.
// ---------------------------------------------------------------------------
#define ARS      144
#define AT_B     (128 * ARS)
#define OFF_Q    0
#define OFF_K    (1 * AT_B)
#define OFF_V    (2 * AT_B)
#define OFF_RPE  (3 * AT_B)
#define OFF_GC   (OFF_RPE + 96 * 4)
#define OFF_ORD  (OFF_GC + 3 * 128 * 4)
#define ASMEM    (OFF_ORD + 128 * 4)     // 57728 B

__global__ __launch_bounds__(256, 2)
void attn_mma(const __half* __restrict__ qkv,
              const int* __restrict__ order, const int* __restrict__ gcoord,
              const float* __restrict__ rpe, __half* __restrict__ oa)
{
    extern __shared__ __align__(128) char sm[];
    const uint32_t smb = smem_u32(sm);
    float* rpeS = (float*)(sm + OFF_RPE);
    int*   gcs  = (int*)(sm + OFF_GC);
    int*   ords = (int*)(sm + OFF_ORD);

    const int w    = blockIdx.x;
    const int hh   = blockIdx.y;
    const int tid  = threadIdx.x;
    const int lane = tid & 31;
    const int wid  = tid >> 5;
    const int wb   = w * PW;

    // ---- stage q/k/v via cp.async (3 tiles x 1024 granules of 16B) ----
    const __half* base = qkv + (size_t)wb * 1536 + hh * 64;
    const __half* srcp[3] = { base, base + 512, base + 1024 };
#pragma unroll
    for (int m = 0; m < 3; m++) {
        uint32_t dstb = smb + m * AT_B;
#pragma unroll
        for (int i = 0; i < 4; i++) {
            int idx = i * 256 + tid;
            int r = idx >> 3, s = idx & 7;
            cp16(dstb + r * ARS + s * 16, srcp[m] + (size_t)r * 1536 + s * 8);
        }
    }
    cp_commit();

    for (int i = tid; i < 128; i += 256) {
        int g = order[wb + i];
        ords[i] = g;
        gcs[0 * 128 + i] = gcoord[g * 3 + 0];
        gcs[1 * 128 + i] = gcoord[g * 3 + 1];
        gcs[2 * 128 + i] = gcoord[g * 3 + 2];
    }
    for (int i = tid; i < 3 * RPEN; i += 256) rpeS[i] = rpe[i * NH + hh];
    cp_wait<0>();
    __syncthreads();

    const int w16   = wid * 16;
    const int arow  = lane & 15;
    const int acolb = (lane >> 4) * 16;
    const int brow  = (lane & 7) + (lane >> 4) * 8;
    const int bkb   = ((lane >> 3) & 1) * 16;

    // ---- S = QK^T : single term ----
    uint32_t q4[4][4];
#pragma unroll
    for (int ks = 0; ks < 4; ks++)
        ldm_x4(q4[ks], smb + OFF_Q + (w16 + arow) * ARS + ks * 32 + acolb);

    float s[16][4];
#pragma unroll
    for (int nj = 0; nj < 16; nj++)
#pragma unroll
        for (int e = 0; e < 4; e++) s[nj][e] = 0.f;

#pragma unroll
    for (int ks = 0; ks < 4; ks++) {
#pragma unroll
        for (int ng = 0; ng < 8; ng++) {
            uint32_t kk[4];
            ldm_x4(kk, smb + OFF_K + (ng * 16 + brow) * ARS + ks * 32 + bkb);
            mma_f16(s[2 * ng],     q4[ks], kk + 0);
            mma_f16(s[2 * ng + 1], q4[ks], kk + 2);
        }
    }

    // ---- scale + RPE bias ----
    const int gr  = lane >> 2;
    const int gc2 = (lane & 3) * 2;
    const int r1  = w16 + gr, r2 = r1 + 8;
    const int qa0 = gcs[0 * 128 + r1], qa1 = gcs[1 * 128 + r1], qa2 = gcs[2 * 128 + r1];
    const int qb0 = gcs[0 * 128 + r2], qb1 = gcs[1 * 128 + r2], qb2 = gcs[2 * 128 + r2];

#pragma unroll
    for (int nj = 0; nj < 16; nj++) {
        int c0 = nj * 8 + gc2;
#pragma unroll
        for (int cc = 0; cc < 2; cc++) {
            int c  = c0 + cc;
            int k0 = gcs[0 * 128 + c], k1 = gcs[1 * 128 + c], k2 = gcs[2 * 128 + c];
            int ia0 = min(max(qa0 - k0, -PBND), PBND) + PBND;
            int ia1 = min(max(qa1 - k1, -PBND), PBND) + PBND + RPEN;
            int ia2 = min(max(qa2 - k2, -PBND), PBND) + PBND + 2 * RPEN;
            int ib0 = min(max(qb0 - k0, -PBND), PBND) + PBND;
            int ib1 = min(max(qb1 - k1, -PBND), PBND) + PBND + RPEN;
            int ib2 = min(max(qb2 - k2, -PBND), PBND) + PBND + 2 * RPEN;
            s[nj][cc]     = s[nj][cc]     * SCALE + rpeS[ia0] + rpeS[ia1] + rpeS[ia2];
            s[nj][2 + cc] = s[nj][2 + cc] * SCALE + rpeS[ib0] + rpeS[ib1] + rpeS[ib2];
        }
    }

    // ---- softmax ----
    float m1 = -1e30f, m2 = -1e30f;
#pragma unroll
    for (int nj = 0; nj < 16; nj++) {
        m1 = fmaxf(m1, fmaxf(s[nj][0], s[nj][1]));
        m2 = fmaxf(m2, fmaxf(s[nj][2], s[nj][3]));
    }
    m1 = fmaxf(m1, __shfl_xor_sync(0xffffffffu, m1, 1));
    m1 = fmaxf(m1, __shfl_xor_sync(0xffffffffu, m1, 2));
    m2 = fmaxf(m2, __shfl_xor_sync(0xffffffffu, m2, 1));
    m2 = fmaxf(m2, __shfl_xor_sync(0xffffffffu, m2, 2));
    float s1 = 0.f, s2 = 0.f;
#pragma unroll
    for (int nj = 0; nj < 16; nj++) {
        s[nj][0] = __expf(s[nj][0] - m1); s1 += s[nj][0];
        s[nj][1] = __expf(s[nj][1] - m1); s1 += s[nj][1];
        s[nj][2] = __expf(s[nj][2] - m2); s2 += s[nj][2];
        s[nj][3] = __expf(s[nj][3] - m2); s2 += s[nj][3];
    }
    s1 += __shfl_xor_sync(0xffffffffu, s1, 1);
    s1 += __shfl_xor_sync(0xffffffffu, s1, 2);
    s2 += __shfl_xor_sync(0xffffffffu, s2, 1);
    s2 += __shfl_xor_sync(0xffffffffu, s2, 2);
    float i1 = 1.0f / s1, i2 = 1.0f / s2;

    // ---- P -> fp16 A-fragments (C-frag == A-frag layout) ----
    uint32_t pa[8][4];
#pragma unroll
    for (int kt = 0; kt < 8; kt++) {
#pragma unroll
        for (int half = 0; half < 2; half++) {
            int f = 2 * kt + half;
            __half2 h01, h23;
            h01.x = __float2half_rn(s[f][0] * i1); h01.y = __float2half_rn(s[f][1] * i1);
            h23.x = __float2half_rn(s[f][2] * i2); h23.y = __float2half_rn(s[f][3] * i2);
            pa[kt][0 + 2 * half] = *(uint32_t*)&h01;
            pa[kt][1 + 2 * half] = *(uint32_t*)&h23;
        }
    }

    // ---- O = P V : single term, V B-frags via ldmatrix.trans ----
    float o[8][4];
#pragma unroll
    for (int nj = 0; nj < 8; nj++)
#pragma unroll
        for (int e = 0; e < 4; e++) o[nj][e] = 0.f;

    const int vrow = ((lane >> 3) & 1) * 8 + (lane & 7);
    const int vcb  = (lane >> 4) * 16;
#pragma unroll
    for (int kt = 0; kt < 8; kt++) {
#pragma unroll
        for (int ng = 0; ng < 4; ng++) {
            uint32_t vv[4];
            ldm_x4_t(vv, smb + OFF_V + (kt * 16 + vrow) * ARS + ng * 32 + vcb);
            mma_f16(o[2 * ng],     pa[kt], vv + 0);
            mma_f16(o[2 * ng + 1], pa[kt], vv + 2);
        }
    }

    // ---- epilogue: single fp16, scatter through order ----
    const int d1 = ords[r1], d2 = ords[r2];
#pragma unroll
    for (int nj = 0; nj < 8; nj++) {
        int col = nj * 8 + gc2;
        __half2 h01, h23;
        h01.x = __float2half_rn(o[nj][0]); h01.y = __float2half_rn(o[nj][1]);
        h23.x = __float2half_rn(o[nj][2]); h23.y = __float2half_rn(o[nj][3]);
        *(__half2*)(oa + (size_t)d1 * 512 + hh * 64 + col) = h01;
        *(__half2*)(oa + (size_t)d2 * 512 + hh * 64 + col) = h23;
    }
}

// ---------------------------------------------------------------------------
extern "C" void kernel_launch(void* const* d_in, const int* in_sizes, int n_in,
                              void* d_out, int out_size)
{
    const float* feat    = (const float*)d_in[0];
    const float* w_qkv   = (const float*)d_in[1];
    const float* b_qkv   = (const float*)d_in[2];
    const float* w_proj  = (const float*)d_in[3];
    const float* b_proj  = (const float*)d_in[4];
    const float* rpe     = (const float*)d_in[5];
    const int*   gcoord  = (const int*)d_in[6];
    const int*   order   = (const int*)d_in[7];
    float*       out     = (float*)d_out;

    __half *qkv, *fa, *aa, *wq, *wph, *wpl;
    cudaGetSymbolAddress((void**)&qkv, g_qkv);
    cudaGetSymbolAddress((void**)&fa,  g_fa);
    cudaGetSymbolAddress((void**)&aa,  g_aa);
    cudaGetSymbolAddress((void**)&wq,  g_wq);
    cudaGetSymbolAddress((void**)&wph, g_wph);
    cudaGetSymbolAddress((void**)&wpl, g_wpl);

    cudaFuncSetAttribute(gemm_f16<1>, cudaFuncAttributeMaxDynamicSharedMemorySize, GSMEM1);
    cudaFuncSetAttribute(gemm_f16<2>, cudaFuncAttributeMaxDynamicSharedMemorySize, GSMEM2);
    cudaFuncSetAttribute(attn_mma, cudaFuncAttributeMaxDynamicSharedMemorySize, ASMEM);

    // 1) fp16 conversions
    tohalf_gather_k<<<NPTS * 128 / 256, 256>>>(feat, order, fa);
    tohalf_plain_k<<<(1536 * 512 / 4) / 256, 256>>>(w_qkv, wq, 1536 * 512 / 4);
    split_plain_k<<<(512 * 512 / 4) / 256, 256>>>(w_proj, wph, wpl, 512 * 512 / 4);

    // 2) QKV projection (1-term fp16) -> serialized qkv single fp16 (bias added)
    gemm_f16<1><<<dim3(1536 / 128, NPTS / 128), 256, GSMEM1>>>(
        fa, wq, nullptr, b_qkv, nullptr, qkv, 1536);

    // 3) fp16 mma attention (1-term); single-fp16 output scattered to point order
    attn_mma<<<dim3(NPTS / PW, NH), 256, ASMEM>>>(
        qkv, order, gcoord, rpe, aa);

    // 4) Output projection (2-term) -> f32 d_out
    gemm_f16<2><<<dim3(512 / 128, NPTS / 128), 256, GSMEM2>>>(
        aa, wph, wpl, b_proj, out, nullptr, 512);
}

// round 11
// speedup vs baseline: 2.4360x; 1.0566x over previous
#include <cuda_runtime.h>
#include <cuda_fp16.h>
#include <stdint.h>

#define NPTS   65536
#define CCH    512
#define NH     8
#define PW     128
#define DHD    64
#define RPEN   31
#define PBND   15
#define SCALE  0.125f

// ---------------------------------------------------------------------------
// Static device scratch (fp16)
// ---------------------------------------------------------------------------
__device__ __half g_qkv[(size_t)NPTS * 1536];   // serialized qkv, single fp16
__device__ __half g_fa [(size_t)NPTS * 512];    // feat[order], single fp16
__device__ __half g_aa [(size_t)NPTS * 512];    // attn-out (point order), single fp16
__device__ __half g_wq [1536 * 512];            // w_qkv single fp16
__device__ __half g_wp [512 * 512];             // w_proj single fp16

// ---------------------------------------------------------------------------
// PTX helpers (sm_100-legal)
// ---------------------------------------------------------------------------
__device__ __forceinline__ uint32_t smem_u32(const void* p) {
    uint32_t a;
    asm("{ .reg .u64 t; cvta.to.shared.u64 t, %1; cvt.u32.u64 %0, t; }"
        : "=r"(a) : "l"(p));
    return a;
}
__device__ __forceinline__ void cp16(uint32_t dst, const void* src) {
    asm volatile("cp.async.cg.shared.global [%0], [%1], 16;"
                 :: "r"(dst), "l"(src) : "memory");
}
__device__ __forceinline__ void cp_commit() {
    asm volatile("cp.async.commit_group;" ::: "memory");
}
template <int N>
__device__ __forceinline__ void cp_wait() {
    asm volatile("cp.async.wait_group %0;" :: "n"(N) : "memory");
}
__device__ __forceinline__ void ldm_x4(uint32_t* r, uint32_t addr) {
    asm volatile("ldmatrix.sync.aligned.m8n8.x4.shared.b16 {%0,%1,%2,%3}, [%4];"
                 : "=r"(r[0]), "=r"(r[1]), "=r"(r[2]), "=r"(r[3]) : "r"(addr));
}
__device__ __forceinline__ void ldm_x4_t(uint32_t* r, uint32_t addr) {
    asm volatile("ldmatrix.sync.aligned.m8n8.x4.trans.shared.b16 {%0,%1,%2,%3}, [%4];"
                 : "=r"(r[0]), "=r"(r[1]), "=r"(r[2]), "=r"(r[3]) : "r"(addr));
}
__device__ __forceinline__ void mma_f16(float* d, const uint32_t* a, const uint32_t* b) {
    asm volatile(
        "mma.sync.aligned.m16n8k16.row.col.f32.f16.f16.f32 "
        "{%0,%1,%2,%3}, {%4,%5,%6,%7}, {%8,%9}, {%0,%1,%2,%3};"
        : "+f"(d[0]), "+f"(d[1]), "+f"(d[2]), "+f"(d[3])
        : "r"(a[0]), "r"(a[1]), "r"(a[2]), "r"(a[3]), "r"(b[0]), "r"(b[1]));
}

// ---------------------------------------------------------------------------
// fp16 conversion kernels
// ---------------------------------------------------------------------------
__global__ void tohalf_gather_k(const float* __restrict__ src, const int* __restrict__ gidx,
                                __half* __restrict__ dst)
{
    int i = blockIdx.x * 256 + threadIdx.x;
    int m = i >> 7;
    int c = (i & 127) << 2;
    float4 v = *(const float4*)(src + (size_t)gidx[m] * 512 + c);
    __align__(8) __half hb[4];
    hb[0] = __float2half_rn(v.x); hb[1] = __float2half_rn(v.y);
    hb[2] = __float2half_rn(v.z); hb[3] = __float2half_rn(v.w);
    *(uint2*)(dst + (size_t)m * 512 + c) = *(uint2*)hb;
}

__global__ void tohalf_plain_k(const float* __restrict__ src, __half* __restrict__ dst, int n4)
{
    int i = blockIdx.x * 256 + threadIdx.x;
    if (i >= n4) return;
    float4 v = *(const float4*)(src + (size_t)i * 4);
    __align__(8) __half hb[4];
    hb[0] = __float2half_rn(v.x); hb[1] = __float2half_rn(v.y);
    hb[2] = __float2half_rn(v.z); hb[3] = __float2half_rn(v.w);
    *(uint2*)(dst + (size_t)i * 4) = *(uint2*)hb;
}

// ---------------------------------------------------------------------------
// fp16 1-term GEMM: C[m][n] = sum_k A[m][k]*B[n][k] + bias[n]
// K=512, tile 128x128, BK=64, 8 warps @ 64x32.
// Output: f32 (C) or single fp16 (Chalf).
// ---------------------------------------------------------------------------
#define GK       512
#define BK       64
#define NCH      (GK / BK)       // 8
#define TROW_B   144             // 128B data + 16B pad
#define TILE_B   (128 * TROW_B)  // 18432
#define GSMEM    (2 * 2 * TILE_B)

__global__ __launch_bounds__(256, 2)
void gemm_f16(const __half* __restrict__ A, const __half* __restrict__ B0,
              const float* __restrict__ bias, float* __restrict__ C,
              __half* __restrict__ Chalf, int Ntot)
{
    extern __shared__ __align__(128) char sm[];
    const uint32_t smb = smem_u32(sm);

    const int tid  = threadIdx.x;
    const int lane = tid & 31;
    const int warp = tid >> 5;
    const int wm   = warp >> 2;
    const int wn   = warp & 3;
    const int m0   = blockIdx.y * 128;
    const int n0   = blockIdx.x * 128;

    const __half* gsrc[2] = { A + (size_t)m0 * GK, B0 + (size_t)n0 * GK };

    auto load_stage = [&](int c) {
        const uint32_t sb = smb + (c & 1) * (2 * TILE_B);
#pragma unroll
        for (int t = 0; t < 2; t++) {
            const __half* g = gsrc[t] + c * BK;
#pragma unroll
            for (int i = 0; i < 4; i++) {
                int idx = i * 256 + tid;
                int r = idx >> 3, s = idx & 7;
                cp16(sb + t * TILE_B + r * TROW_B + s * 16,
                     g + (size_t)r * GK + s * 8);
            }
        }
    };

    float acc[4][4][4];
#pragma unroll
    for (int i = 0; i < 4; i++)
#pragma unroll
        for (int j = 0; j < 4; j++)
#pragma unroll
            for (int e = 0; e < 4; e++) acc[i][j][e] = 0.f;

    const int arow  = lane & 15;
    const int acolb = (lane >> 4) * 16;
    const int brow  = (lane & 7) + (lane >> 4) * 8;
    const int bkb   = ((lane >> 3) & 1) * 16;

    load_stage(0);
    cp_commit();

    for (int c = 0; c < NCH; c++) {
        if (c + 1 < NCH) { load_stage(c + 1); cp_commit(); cp_wait<1>(); }
        else             { cp_wait<0>(); }
        __syncthreads();

        const uint32_t sb  = smb + (c & 1) * (2 * TILE_B);
        const uint32_t sA  = sb;
        const uint32_t sB0 = sb + TILE_B;

#pragma unroll
        for (int ks = 0; ks < 4; ks++) {
            const int kb = ks * 32;
            uint32_t ah[4][4], b0[2][4];
#pragma unroll
            for (int mi = 0; mi < 4; mi++)
                ldm_x4(ah[mi], sA + (wm * 64 + mi * 16 + arow) * TROW_B + kb + acolb);
#pragma unroll
            for (int jj = 0; jj < 2; jj++)
                ldm_x4(b0[jj], sB0 + (wn * 32 + jj * 16 + brow) * TROW_B + kb + bkb);
#pragma unroll
            for (int mi = 0; mi < 4; mi++)
#pragma unroll
                for (int nj = 0; nj < 4; nj++)
                    mma_f16(acc[mi][nj], ah[mi], &b0[nj >> 1][(nj & 1) * 2]);
        }
        if (c + 1 < NCH) __syncthreads();
    }

    const int gr = lane >> 2;
    const int gc = (lane & 3) * 2;
    float2 bv[4];
#pragma unroll
    for (int nj = 0; nj < 4; nj++)
        bv[nj] = *(const float2*)(bias + n0 + wn * 32 + nj * 8 + gc);

    if (Chalf) {
#pragma unroll
        for (int mi = 0; mi < 4; mi++) {
            int rowa = m0 + wm * 64 + mi * 16 + gr;
#pragma unroll
            for (int nj = 0; nj < 4; nj++) {
                int col = n0 + wn * 32 + nj * 8 + gc;
                __half2 h01, h23;
                h01.x = __float2half_rn(acc[mi][nj][0] + bv[nj].x);
                h01.y = __float2half_rn(acc[mi][nj][1] + bv[nj].y);
                h23.x = __float2half_rn(acc[mi][nj][2] + bv[nj].x);
                h23.y = __float2half_rn(acc[mi][nj][3] + bv[nj].y);
                *(__half2*)(Chalf + (size_t)rowa * Ntot + col)       = h01;
                *(__half2*)(Chalf + (size_t)(rowa + 8) * Ntot + col) = h23;
            }
        }
    } else {
#pragma unroll
        for (int mi = 0; mi < 4; mi++) {
            int rowa = m0 + wm * 64 + mi * 16 + gr;
#pragma unroll
            for (int nj = 0; nj < 4; nj++) {
                int col = n0 + wn * 32 + nj * 8 + gc;
                float2 lo = make_float2(acc[mi][nj][0] + bv[nj].x, acc[mi][nj][1] + bv[nj].y);
                float2 hi = make_float2(acc[mi][nj][2] + bv[nj].x, acc[mi][nj][3] + bv[nj].y);
                *(float2*)(C + (size_t)rowa * Ntot + col)       = lo;
                *(float2*)(C + (size_t)(rowa + 8) * Ntot + col) = hi;
            }
        }
    }
}

// ---------------------------------------------------------------------------
// fp16 mma attention per (window, head). Single-term QK^T and PV.
// RPE indices via packed-byte SIMD (__vsubss4 / __vmaxs4 / __vmins4).
// ---------------------------------------------------------------------------
#define ARS      144
#define AT_B     (128 * ARS)
#define OFF_Q    0
#define OFF_K    (1 * AT_B)
#define OFF_V    (2 * AT_B)
#define OFF_RPE  (3 * AT_B)
#define OFF_GC   (OFF_RPE + 96 * 4)      // packed coords: 128 u32
#define OFF_ORD  (OFF_GC + 128 * 4)
#define ASMEM    (OFF_ORD + 128 * 4)     // 56704 B

__global__ __launch_bounds__(256, 2)
void attn_mma(const __half* __restrict__ qkv,
              const int* __restrict__ order, const int* __restrict__ gcoord,
              const float* __restrict__ rpe, __half* __restrict__ oa)
{
    extern __shared__ __align__(128) char sm[];
    const uint32_t smb = smem_u32(sm);
    float*    rpeS = (float*)(sm + OFF_RPE);
    uint32_t* pcs  = (uint32_t*)(sm + OFF_GC);   // packed (x|y<<8|z<<16)
    int*      ords = (int*)(sm + OFF_ORD);

    const int w    = blockIdx.x;
    const int hh   = blockIdx.y;
    const int tid  = threadIdx.x;
    const int lane = tid & 31;
    const int wid  = tid >> 5;
    const int wb   = w * PW;

    // ---- stage q/k/v via cp.async ----
    const __half* base = qkv + (size_t)wb * 1536 + hh * 64;
    const __half* srcp[3] = { base, base + 512, base + 1024 };
#pragma unroll
    for (int m = 0; m < 3; m++) {
        uint32_t dstb = smb + m * AT_B;
#pragma unroll
        for (int i = 0; i < 4; i++) {
            int idx = i * 256 + tid;
            int r = idx >> 3, s = idx & 7;
            cp16(dstb + r * ARS + s * 16, srcp[m] + (size_t)r * 1536 + s * 8);
        }
    }
    cp_commit();

    for (int i = tid; i < 128; i += 256) {
        int g = order[wb + i];
        ords[i] = g;
        uint32_t x = (uint32_t)gcoord[g * 3 + 0] & 0xFF;
        uint32_t y = (uint32_t)gcoord[g * 3 + 1] & 0xFF;
        uint32_t z = (uint32_t)gcoord[g * 3 + 2] & 0xFF;
        pcs[i] = x | (y << 8) | (z << 16);
    }
    for (int i = tid; i < 3 * RPEN; i += 256) rpeS[i] = rpe[i * NH + hh];
    cp_wait<0>();
    __syncthreads();

    const int w16   = wid * 16;
    const int arow  = lane & 15;
    const int acolb = (lane >> 4) * 16;
    const int brow  = (lane & 7) + (lane >> 4) * 8;
    const int bkb   = ((lane >> 3) & 1) * 16;

    // ---- S = QK^T : single term ----
    uint32_t q4[4][4];
#pragma unroll
    for (int ks = 0; ks < 4; ks++)
        ldm_x4(q4[ks], smb + OFF_Q + (w16 + arow) * ARS + ks * 32 + acolb);

    float s[16][4];
#pragma unroll
    for (int nj = 0; nj < 16; nj++)
#pragma unroll
        for (int e = 0; e < 4; e++) s[nj][e] = 0.f;

#pragma unroll
    for (int ks = 0; ks < 4; ks++) {
#pragma unroll
        for (int ng = 0; ng < 8; ng++) {
            uint32_t kk[4];
            ldm_x4(kk, smb + OFF_K + (ng * 16 + brow) * ARS + ks * 32 + bkb);
            mma_f16(s[2 * ng],     q4[ks], kk + 0);
            mma_f16(s[2 * ng + 1], q4[ks], kk + 2);
        }
    }

    // ---- scale + RPE bias (packed-byte SIMD index math) ----
    const int gr  = lane >> 2;
    const int gc2 = (lane & 3) * 2;
    const int r1  = w16 + gr, r2 = r1 + 8;
    const uint32_t pq1 = pcs[r1], pq2 = pcs[r2];
    const uint32_t NEG15 = 0xF1F1F1F1u, POS15 = 0x0F0F0F0Fu;

#pragma unroll
    for (int nj = 0; nj < 16; nj++) {
        int c0 = nj * 8 + gc2;
#pragma unroll
        for (int cc = 0; cc < 2; cc++) {
            uint32_t pk = pcs[c0 + cc];
            uint32_t da = __vadd4(__vmins4(__vmaxs4(__vsubss4(pq1, pk), NEG15), POS15), POS15);
            uint32_t db = __vadd4(__vmins4(__vmaxs4(__vsubss4(pq2, pk), NEG15), POS15), POS15);
            float ba = rpeS[da & 0xFF] + rpeS[((da >> 8) & 0xFF) + RPEN]
                     + rpeS[((da >> 16) & 0xFF) + 2 * RPEN];
            float bb = rpeS[db & 0xFF] + rpeS[((db >> 8) & 0xFF) + RPEN]
                     + rpeS[((db >> 16) & 0xFF) + 2 * RPEN];
            s[nj][cc]     = s[nj][cc]     * SCALE + ba;
            s[nj][2 + cc] = s[nj][2 + cc] * SCALE + bb;
        }
    }

    // ---- softmax ----
    float m1 = -1e30f, m2 = -1e30f;
#pragma unroll
    for (int nj = 0; nj < 16; nj++) {
        m1 = fmaxf(m1, fmaxf(s[nj][0], s[nj][1]));
        m2 = fmaxf(m2, fmaxf(s[nj][2], s[nj][3]));
    }
    m1 = fmaxf(m1, __shfl_xor_sync(0xffffffffu, m1, 1));
    m1 = fmaxf(m1, __shfl_xor_sync(0xffffffffu, m1, 2));
    m2 = fmaxf(m2, __shfl_xor_sync(0xffffffffu, m2, 1));
    m2 = fmaxf(m2, __shfl_xor_sync(0xffffffffu, m2, 2));
    float s1 = 0.f, s2 = 0.f;
#pragma unroll
    for (int nj = 0; nj < 16; nj++) {
        s[nj][0] = __expf(s[nj][0] - m1); s1 += s[nj][0];
        s[nj][1] = __expf(s[nj][1] - m1); s1 += s[nj][1];
        s[nj][2] = __expf(s[nj][2] - m2); s2 += s[nj][2];
        s[nj][3] = __expf(s[nj][3] - m2); s2 += s[nj][3];
    }
    s1 += __shfl_xor_sync(0xffffffffu, s1, 1);
    s1 += __shfl_xor_sync(0xffffffffu, s1, 2);
    s2 += __shfl_xor_sync(0xffffffffu, s2, 1);
    s2 += __shfl_xor_sync(0xffffffffu, s2, 2);
    float i1 = 1.0f / s1, i2 = 1.0f / s2;

    // ---- P -> fp16 A-fragments ----
    uint32_t pa[8][4];
#pragma unroll
    for (int kt = 0; kt < 8; kt++) {
#pragma unroll
        for (int half = 0; half < 2; half++) {
            int f = 2 * kt + half;
            __half2 h01, h23;
            h01.x = __float2half_rn(s[f][0] * i1); h01.y = __float2half_rn(s[f][1] * i1);
            h23.x = __float2half_rn(s[f][2] * i2); h23.y = __float2half_rn(s[f][3] * i2);
            pa[kt][0 + 2 * half] = *(uint32_t*)&h01;
            pa[kt][1 + 2 * half] = *(uint32_t*)&h23;
        }
    }

    // ---- O = P V : single term ----
    float o[8][4];
#pragma unroll
    for (int nj = 0; nj < 8; nj++)
#pragma unroll
        for (int e = 0; e < 4; e++) o[nj][e] = 0.f;

    const int vrow = ((lane >> 3) & 1) * 8 + (lane & 7);
    const int vcb  = (lane >> 4) * 16;
#pragma unroll
    for (int kt = 0; kt < 8; kt++) {
#pragma unroll
        for (int ng = 0; ng < 4; ng++) {
            uint32_t vv[4];
            ldm_x4_t(vv, smb + OFF_V + (kt * 16 + vrow) * ARS + ng * 32 + vcb);
            mma_f16(o[2 * ng],     pa[kt], vv + 0);
            mma_f16(o[2 * ng + 1], pa[kt], vv + 2);
        }
    }

    // ---- epilogue: single fp16, scatter through order ----
    const int d1 = ords[r1], d2 = ords[r2];
#pragma unroll
    for (int nj = 0; nj < 8; nj++) {
        int col = nj * 8 + gc2;
        __half2 h01, h23;
        h01.x = __float2half_rn(o[nj][0]); h01.y = __float2half_rn(o[nj][1]);
        h23.x = __float2half_rn(o[nj][2]); h23.y = __float2half_rn(o[nj][3]);
        *(__half2*)(oa + (size_t)d1 * 512 + hh * 64 + col) = h01;
        *(__half2*)(oa + (size_t)d2 * 512 + hh * 64 + col) = h23;
    }
}

// ---------------------------------------------------------------------------
extern "C" void kernel_launch(void* const* d_in, const int* in_sizes, int n_in,
                              void* d_out, int out_size)
{
    const float* feat    = (const float*)d_in[0];
    const float* w_qkv   = (const float*)d_in[1];
    const float* b_qkv   = (const float*)d_in[2];
    const float* w_proj  = (const float*)d_in[3];
    const float* b_proj  = (const float*)d_in[4];
    const float* rpe     = (const float*)d_in[5];
    const int*   gcoord  = (const int*)d_in[6];
    const int*   order   = (const int*)d_in[7];
    float*       out     = (float*)d_out;

    __half *qkv, *fa, *aa, *wq, *wp;
    cudaGetSymbolAddress((void**)&qkv, g_qkv);
    cudaGetSymbolAddress((void**)&fa,  g_fa);
    cudaGetSymbolAddress((void**)&aa,  g_aa);
    cudaGetSymbolAddress((void**)&wq,  g_wq);
    cudaGetSymbolAddress((void**)&wp,  g_wp);

    cudaFuncSetAttribute(gemm_f16, cudaFuncAttributeMaxDynamicSharedMemorySize, GSMEM);
    cudaFuncSetAttribute(attn_mma, cudaFuncAttributeMaxDynamicSharedMemorySize, ASMEM);

    // 1) fp16 conversions
    tohalf_gather_k<<<NPTS * 128 / 256, 256>>>(feat, order, fa);
    tohalf_plain_k<<<(1536 * 512 / 4) / 256, 256>>>(w_qkv, wq, 1536 * 512 / 4);
    tohalf_plain_k<<<(512 * 512 / 4) / 256, 256>>>(w_proj, wp, 512 * 512 / 4);

    // 2) QKV projection (1-term) -> serialized qkv fp16 (bias added)
    gemm_f16<<<dim3(1536 / 128, NPTS / 128), 256, GSMEM>>>(
        fa, wq, b_qkv, nullptr, qkv, 1536);

    // 3) fp16 mma attention; fp16 output scattered to point order
    attn_mma<<<dim3(NPTS / PW, NH), 256, ASMEM>>>(
        qkv, order, gcoord, rpe, aa);

    // 4) Output projection (1-term) -> f32 d_out
    gemm_f16<<<dim3(512 / 128, NPTS / 128), 256, GSMEM>>>(
        aa, wp, b_proj, out, nullptr, 512);
}